// round 15
// baseline (speedup 1.0000x reference)
#include <cuda_runtime.h>
#include <cuda_bf16.h>
#include <math.h>

#define NB 8
#define NPIX 16384
#define N_OUT 2
#define N_IN 6
typedef unsigned long long u64;
typedef unsigned int u32;
typedef unsigned short u16;

// ---------------- scratch (static device globals) ----------------
__device__ float g_t4[NB*4*NPIX];
__device__ float g_t8[NB*8*NPIX];
__device__ float g_mask2[NB*NPIX*128];          // channel-last [b][pix][128]
__device__ float g_b[NB*NPIX], g_r[NB*NPIX], g_p[NB*NPIX], g_Bp[NB*NPIX];
// channel-last bf16 hi/lo planes
__device__ __nv_bfloat16 g_t8h[NB*NPIX*8], g_t8l[NB*NPIX*8];
__device__ __nv_bfloat16 g_ah[NB*NPIX*128], g_al[NB*NPIX*128];
__device__ __nv_bfloat16 g_bh[NB*NPIX*128], g_bl[NB*NPIX*128];
// bf16 weight images for tconv: per chunk [hi 128x64][lo 128x64] row-major
__device__ __nv_bfloat16 g_wb_w12[11*2*8192], g_wb_m12[11*2*8192];
__device__ __nv_bfloat16 g_wb_m2 [18*2*8192], g_wb_m3 [18*2*8192];
// fragment-ordered adjoint weights: [81 tap][8 k16][32 lane][2 reg] u32
__device__ u32 g_wadj_h[41472], g_wadj_l[41472];
__device__ float g_lam[NB], g_inv1pl[NB], g_scaling[NB*128];
__device__ float g_partA[NB*16], g_partB1[NB*64], g_partB2[NB*64];

// ---------------- PTX helpers (baseline PTX only) ----------------
__device__ __forceinline__ u32 smem_u32(const void* p){
    u32 a; asm("{ .reg .u64 t; cvta.to.shared.u64 t, %1; cvt.u32.u64 %0, t; }":"=r"(a):"l"(p)); return a;
}
__device__ __forceinline__ void cp16(u32 dst, const void* src, bool pred){
    int sz = pred ? 16 : 0;
    asm volatile("cp.async.ca.shared.global [%0], [%1], 16, %2;"
                 :: "r"(dst), "l"(src), "r"(sz) : "memory");
}
__device__ __forceinline__ void cp_commit(){ asm volatile("cp.async.commit_group;":::"memory"); }
template<int N> __device__ __forceinline__ void cp_wait(){
    asm volatile("cp.async.wait_group %0;"::"n"(N):"memory");
}
__device__ __forceinline__ void ldsm4(u32* r, u32 addr){
    asm volatile("ldmatrix.sync.aligned.m8n8.x4.shared.b16 {%0,%1,%2,%3}, [%4];"
                 : "=r"(r[0]),"=r"(r[1]),"=r"(r[2]),"=r"(r[3]) : "r"(addr));
}
__device__ __forceinline__ void mma_bf16(float* c, const u32* a, const u32* b){
    asm volatile("mma.sync.aligned.m16n8k16.row.col.f32.bf16.bf16.f32 "
                 "{%0,%1,%2,%3}, {%4,%5,%6,%7}, {%8,%9}, {%0,%1,%2,%3};"
                 : "+f"(c[0]),"+f"(c[1]),"+f"(c[2]),"+f"(c[3])
                 : "r"(a[0]),"r"(a[1]),"r"(a[2]),"r"(a[3]), "r"(b[0]),"r"(b[1]));
}

// ---------------- splines / split ----------------
__device__ __forceinline__ float spline_gen(const float* __restrict__ c, int K,
                                            float xmin, float xmax, float x){
    float step=(xmax-xmin)/(float)(K-1);
    float t=(x-xmin)/step, f=floorf(t);
    f=fminf(fmaxf(f,0.0f),(float)(K-2));
    int i=(int)f; float fr=t-f;
    return fmaf(fr, c[i+1]-c[i], c[i]);
}
__device__ __forceinline__ float spline31(const float* __restrict__ c, float v){
    float t=v*10.0f, f=floorf(t);
    f=fminf(fmaxf(f,0.0f),29.0f);
    int i=(int)f; float fr=t-f;
    return fmaf(fr, c[i+1]-c[i], c[i]);
}
__device__ __forceinline__ void bfsplit(float v, u16& h, u16& l){
    __nv_bfloat16 hb=__float2bfloat16_rn(v);
    h=__bfloat16_as_ushort(hb);
    l=__bfloat16_as_ushort(__float2bfloat16_rn(v-__bfloat162float(hb)));
}

// ============ 9x9 CIN=8 fwd tconv: resident halo A, double-buffered B ============
// EPI: 1 = spline31(|v|) -> bf16 hi/lo channel-last,
//      3 = multiply by mask2 (channel-last fp32) -> bf16 hi/lo channel-last
template<int EPI>
__global__ void __launch_bounds__(256)
tconv9_k(const __nv_bfloat16* __restrict__ inh, const __nv_bfloat16* __restrict__ inl,
         const __nv_bfloat16* __restrict__ wb,
         __nv_bfloat16* __restrict__ outh, __nv_bfloat16* __restrict__ outl,
         const float* __restrict__ spc, const float* __restrict__ maskp)
{
    constexpr int HALO = 1024;
    constexpr int BB   = 16384;
    constexpr int BPL  = 18432;
    constexpr int BBUF = 2*BPL;

    extern __shared__ char s_raw[];
    const u32 sb = smem_u32(s_raw);
    float* hdr = (float*)s_raw;
    const int tid = threadIdx.x, wid = tid>>5, lid = tid&31;
    const int x0 = blockIdx.x*16, y0 = blockIdx.y*8, b = blockIdx.z;

    if (EPI==1 && tid<31) hdr[tid] = spc[tid];

    for (int i=tid; i<768; i+=256){
        int pl = (i>=384), px = i - pl*384;
        int iy = px/24, ix = px - iy*24;
        int gy = y0+iy-4, gx = x0+ix-4;
        bool ok = ((u32)gy<128u) && ((u32)gx<128u);
        const __nv_bfloat16* srcb = pl ? inl : inh;
        const void* src = ok ? (const void*)(srcb + ((b*128+gy)*128+gx)*8) : (const void*)srcb;
        cp16(sb + HALO + (u32)(pl*6400 + iy*400 + ix*16), src, ok);
    }
    auto stageB = [&](int c, int buf){
#pragma unroll
        for (int it=0; it<8; ++it){
            int idx = tid + it*256;
            int pl = idx>>10, r = idx&1023;
            int n = r>>3, s = r&7;
            const __nv_bfloat16* src = wb + c*16384 + pl*8192 + n*64 + s*8;
            cp16(sb + BB + (u32)(buf*BBUF + pl*BPL + n*144 + s*16), src, true);
        }
        cp_commit();
    };

    float acc[8][2][4];
#pragma unroll
    for (int i=0;i<8;++i)
#pragma unroll
        for (int j=0;j<2;++j)
#pragma unroll
            for (int k=0;k<4;++k) acc[i][j][k]=0.0f;

    const int rr = lid & 7, t = lid >> 3;
    const int mx = rr + (t&1)*8;
    const u32 bOff = (u32)((wid*16 + (t>>1)*8 + rr)*144 + (t&1)*16);

    stageB(0, 0);
#pragma unroll 1
    for (int c=0; c<11; ++c){
        const int buf = c&1;
        if (c+1 < 11){ stageB(c+1, buf^1); cp_wait<1>(); }
        else         { cp_wait<0>(); }
        __syncthreads();

        const u32 bH = sb + BB + buf*BBUF, bL = bH + BPL;
#pragma unroll
        for (int k16=0; k16<4; ++k16){
            u32 bh[4], bl[4];
            ldsm4(bh, bH + bOff + k16*32);
            ldsm4(bl, bL + bOff + k16*32);
            int ta = c*8 + k16*2, tb = ta + 1;
            if (ta>80) ta=80;
            if (tb>80) tb=80;
            int tap = (t>>1) ? tb : ta;
            int ky = tap/9, kx = tap - ky*9;
            const u32 aBase = sb + HALO + (u32)(ky*400 + (mx + kx)*16);
#pragma unroll
            for (int mt=0; mt<8; ++mt){
                u32 ah[4], al[4];
                ldsm4(ah, aBase + (u32)(mt*400));
                ldsm4(al, aBase + (u32)(mt*400) + 6400u);
                mma_bf16(acc[mt][0], ah, bh+0);
                mma_bf16(acc[mt][1], ah, bh+2);
                mma_bf16(acc[mt][0], al, bh+0);
                mma_bf16(acc[mt][1], al, bh+2);
                mma_bf16(acc[mt][0], ah, bl+0);
                mma_bf16(acc[mt][1], ah, bl+2);
            }
        }
        __syncthreads();
    }

    const int row = lid>>2, q = (lid&3)*2;
#pragma unroll
    for (int mt=0; mt<8; ++mt){
        const int gy = y0 + mt;
        const int gxa = x0 + row, gxb = gxa + 8;
#pragma unroll
        for (int nt=0; nt<2; ++nt){
            const int n = wid*16 + nt*8 + q;
            const int pa = (b*128+gy)*128+gxa, pb = (b*128+gy)*128+gxb;
            float v0 = acc[mt][nt][0], v1 = acc[mt][nt][1];
            float v2 = acc[mt][nt][2], v3 = acc[mt][nt][3];
            if (EPI==1){
                v0 = spline31(hdr, fabsf(v0)); v1 = spline31(hdr, fabsf(v1));
                v2 = spline31(hdr, fabsf(v2)); v3 = spline31(hdr, fabsf(v3));
            } else {
                float2 m0 = *(const float2*)(maskp + (long)pa*128 + n);
                float2 m1 = *(const float2*)(maskp + (long)pb*128 + n);
                v0 *= m0.x; v1 *= m0.y;
                v2 *= m1.x; v3 *= m1.y;
            }
            u16 h0,l0,h1,l1,h2,l2,h3,l3;
            bfsplit(v0,h0,l0); bfsplit(v1,h1,l1);
            bfsplit(v2,h2,l2); bfsplit(v3,h3,l3);
            *(u32*)(outh + (long)pa*128 + n) = (u32)h0 | ((u32)h1<<16);
            *(u32*)(outl + (long)pa*128 + n) = (u32)l0 | ((u32)l1<<16);
            *(u32*)(outh + (long)pb*128 + n) = (u32)h2 | ((u32)h3<<16);
            *(u32*)(outl + (long)pb*128 + n) = (u32)l2 | ((u32)l3<<16);
        }
    }
}

// ============ 3x3 CIN=128 tconv: 32-k chunks (pitch 80) ============
// EPI: 1 = spline31(|v|)->bf16 hi/lo channel-last, 2 = mask final -> fp32 channel-last
template<int EPI>
__global__ void __launch_bounds__(256)
tconv3_k(const __nv_bfloat16* __restrict__ inh, const __nv_bfloat16* __restrict__ inl,
         const __nv_bfloat16* __restrict__ wb, float* __restrict__ outf,
         __nv_bfloat16* __restrict__ outh, __nv_bfloat16* __restrict__ outl,
         const float* __restrict__ spc)
{
    constexpr int NKC   = 36;
    constexpr int HDR   = 1024;
    constexpr int PLANE = 128*80;
    constexpr int BUF   = 2*PLANE;
    constexpr int SM_A  = HDR;
    constexpr int SM_B  = HDR + 2*BUF;

    extern __shared__ char s_raw[];
    const u32 sb = smem_u32(s_raw);
    float* hdr = (float*)s_raw;
    const int tid = threadIdx.x, wid = tid>>5, lid = tid&31;
    const int x0 = blockIdx.x*16, y0 = blockIdx.y*8, b = blockIdx.z;

    if (tid<31) hdr[tid] = spc[tid];
    if (EPI==2 && tid>=64 && tid<192) hdr[32+tid-64] = g_scaling[b*128+tid-64];

    auto stage = [&](int c, int buf){
        const int tap = c>>2, q = c&3;
        const int ky = tap/3, kx = tap%3;
        const int c64 = c>>1, h = c&1;
#pragma unroll
        for (int it=0; it<4; ++it){
            int idx = tid + it*256;
            int pl = idx>>9, r = idx&511;
            int m = r>>2, s = r&3;
            int my = m>>4, mxx = m&15;
            const __nv_bfloat16* srcb = pl ? inl : inh;
            const void* src = srcb; bool ok = false;
            int gy = y0+my+ky-1, gx = x0+mxx+kx-1;
            if ((u32)gy<128u && (u32)gx<128u){
                ok = true; src = srcb + ((b*128+gy)*128+gx)*128 + q*32 + s*8;
            }
            cp16(sb + SM_A + buf*BUF + pl*PLANE + m*80 + s*16, src, ok);
        }
#pragma unroll
        for (int it=0; it<4; ++it){
            int idx = tid + it*256;
            int pl = idx>>9, r = idx&511;
            int n = r>>2, s = r&3;
            const __nv_bfloat16* src = wb + c64*16384 + pl*8192 + n*64 + h*32 + s*8;
            cp16(sb + SM_B + buf*BUF + pl*PLANE + n*80 + s*16, src, true);
        }
        cp_commit();
    };

    float acc[8][2][4];
#pragma unroll
    for (int i=0;i<8;++i)
#pragma unroll
        for (int j=0;j<2;++j)
#pragma unroll
            for (int k=0;k<4;++k) acc[i][j][k]=0.0f;

    const int rr = lid & 7, t = lid >> 3;
    const u32 aOff = (u32)((rr + (t&1)*8)*80 + (t>>1)*16);
    const u32 bOff = (u32)((wid*16 + (t>>1)*8 + rr)*80 + (t&1)*16);

    stage(0, 0);
#pragma unroll 1
    for (int c=0; c<NKC; ++c){
        const int buf = c&1;
        if (c+1 < NKC){ stage(c+1, buf^1); cp_wait<1>(); }
        else          { cp_wait<0>(); }
        __syncthreads();

        const u32 aH = sb + SM_A + buf*BUF, aL = aH + PLANE;
        const u32 bH = sb + SM_B + buf*BUF, bL = bH + PLANE;
#pragma unroll
        for (int k16=0; k16<2; ++k16){
            u32 bh[4], bl[4];
            ldsm4(bh, bH + bOff + k16*32);
            ldsm4(bl, bL + bOff + k16*32);
#pragma unroll
            for (int mt=0; mt<8; ++mt){
                u32 ah[4], al[4];
                ldsm4(ah, aH + aOff + mt*1280 + k16*32);
                ldsm4(al, aL + aOff + mt*1280 + k16*32);
                mma_bf16(acc[mt][0], ah, bh+0);
                mma_bf16(acc[mt][1], ah, bh+2);
                mma_bf16(acc[mt][0], al, bh+0);
                mma_bf16(acc[mt][1], al, bh+2);
                mma_bf16(acc[mt][0], ah, bl+0);
                mma_bf16(acc[mt][1], ah, bl+2);
            }
        }
        __syncthreads();
    }

    const int row = lid>>2, q = (lid&3)*2;
#pragma unroll
    for (int mt=0; mt<8; ++mt){
        const int gy = y0 + mt;
        const int gxa = x0 + row, gxb = gxa + 8;
#pragma unroll
        for (int nt=0; nt<2; ++nt){
            const int n = wid*16 + nt*8 + q;
            const int pa = (b*128+gy)*128+gxa, pb = (b*128+gy)*128+gxb;
            float v0 = acc[mt][nt][0], v1 = acc[mt][nt][1];
            float v2 = acc[mt][nt][2], v3 = acc[mt][nt][3];
            if (EPI==1){
                v0 = spline31(hdr, fabsf(v0)); v1 = spline31(hdr, fabsf(v1));
                v2 = spline31(hdr, fabsf(v2)); v3 = spline31(hdr, fabsf(v3));
                u16 h0,l0,h1,l1,h2,l2,h3,l3;
                bfsplit(v0,h0,l0); bfsplit(v1,h1,l1);
                bfsplit(v2,h2,l2); bfsplit(v3,h3,l3);
                *(u32*)(outh + (long)pa*128 + n) = (u32)h0 | ((u32)h1<<16);
                *(u32*)(outl + (long)pa*128 + n) = (u32)l0 | ((u32)l1<<16);
                *(u32*)(outh + (long)pb*128 + n) = (u32)h2 | ((u32)h3<<16);
                *(u32*)(outl + (long)pb*128 + n) = (u32)l2 | ((u32)l3<<16);
            } else {
                float s0 = hdr[32+n], s1 = hdr[32+n+1];
                v0 = spline31(hdr, s0*fabsf(v0)); v0 = fminf(fmaxf(v0,0.01f),1.0f); v0 *= v0;
                v1 = spline31(hdr, s1*fabsf(v1)); v1 = fminf(fmaxf(v1,0.01f),1.0f); v1 *= v1;
                v2 = spline31(hdr, s0*fabsf(v2)); v2 = fminf(fmaxf(v2,0.01f),1.0f); v2 *= v2;
                v3 = spline31(hdr, s1*fabsf(v3)); v3 = fminf(fmaxf(v3,0.01f),1.0f); v3 *= v3;
                float2 w0v; w0v.x=v0; w0v.y=v1;
                float2 w1v; w1v.x=v2; w1v.y=v3;
                *(float2*)(outf + (long)pa*128 + n) = w0v;
                *(float2*)(outf + (long)pb*128 + n) = w1v;
            }
        }
    }
}

// ============ adjoint conv 128->8 via mma.sync, ci split in 2 halves ============
// R15: 6 independent accumulator chains (3 split-terms x kk-parity) to break the
// single-accumulator RAW dependency (ncu R14: tensor 21.6%, issue 17% -> latency-bound),
// plus per-tap weight prefetch (8 uint2 up front).
__global__ void __launch_bounds__(256)
tadj_k(const __nv_bfloat16* __restrict__ mh, const __nv_bfloat16* __restrict__ ml,
       float* __restrict__ out8)
{
    extern __shared__ char s_raw[];
    const u32 sb = smem_u32(s_raw);
    const int tid = threadIdx.x, wid = tid>>5, lid = tid&31;
    const int x0 = blockIdx.x*16, y0 = blockIdx.y*8, b = blockIdx.z;

    float a0[4]={0,0,0,0}, a1[4]={0,0,0,0}, a2[4]={0,0,0,0};
    float a3[4]={0,0,0,0}, a4[4]={0,0,0,0}, a5[4]={0,0,0,0};
    const int rr = lid&7, t = lid>>3;
    const int rowSel = rr + (t&1)*8;
    const u32 colSel = (u32)((t>>1)*16);

    const uint2* __restrict__ whv = (const uint2*)g_wadj_h;
    const uint2* __restrict__ wlv = (const uint2*)g_wadj_l;

#pragma unroll 1
    for (int h=0; h<2; ++h){
        for (int i=tid; i<6144; i+=256){
            int px = i>>4, r = i&15, pl = r>>3, seg = r&7;
            int iy = px/24, ix = px - iy*24;
            int gy = y0+iy-4, gx = x0+ix-4;
            bool ok = ((u32)gy<128u) && ((u32)gx<128u);
            const __nv_bfloat16* srcb = pl ? ml : mh;
            const void* src = ok ? (const void*)(srcb + (((long)(b*128+gy)*128+gx)*128 + h*64 + seg*8))
                                 : (const void*)srcb;
            cp16(sb + (u32)(px*272 + pl*128 + seg*16), src, ok);
        }
        cp_commit(); cp_wait<0>();
        __syncthreads();

#pragma unroll 1
        for (int tap=0; tap<81; ++tap){
            int ky = tap/9, kx = tap - ky*9;
            const u32 base = sb + (u32)(((wid+ky)*24 + rowSel + kx)*272) + colSel;
            const uint2* bh = whv + tap*256 + h*128 + lid;
            const uint2* bl = wlv + tap*256 + h*128 + lid;
            // prefetch all 8 weight fragments for this tap
            uint2 wv[4][2];
#pragma unroll
            for (int kk=0; kk<4; ++kk){
                wv[kk][0] = __ldg(bh + kk*32);
                wv[kk][1] = __ldg(bl + kk*32);
            }
#pragma unroll
            for (int kk=0; kk<4; ++kk){
                u32 ah[4], al[4];
                ldsm4(ah, base + kk*32);
                ldsm4(al, base + 128 + kk*32);
                if (kk & 1){
                    mma_bf16(a3, ah, (const u32*)&wv[kk][0]);
                    mma_bf16(a4, al, (const u32*)&wv[kk][0]);
                    mma_bf16(a5, ah, (const u32*)&wv[kk][1]);
                } else {
                    mma_bf16(a0, ah, (const u32*)&wv[kk][0]);
                    mma_bf16(a1, al, (const u32*)&wv[kk][0]);
                    mma_bf16(a2, ah, (const u32*)&wv[kk][1]);
                }
            }
        }
        __syncthreads();
    }

    const int xr = lid>>2, co = (lid&3)*2;
    const int gy = y0 + wid;
    float* o0 = out8 + ((b*8+co)*128 + gy)*128 + x0;
    float* o1 = o0 + NPIX;
    float r0 = ((a0[0]+a1[0])+(a2[0]+a3[0]))+(a4[0]+a5[0]);
    float r1 = ((a0[1]+a1[1])+(a2[1]+a3[1]))+(a4[1]+a5[1]);
    float r2 = ((a0[2]+a1[2])+(a2[2]+a3[2]))+(a4[2]+a5[2]);
    float r3 = ((a0[3]+a1[3])+(a2[3]+a3[3]))+(a4[3]+a5[3]);
    o0[xr]   = r0; o1[xr]   = r1;
    o0[xr+8] = r2; o1[xr+8] = r3;
}

// ============ weight prep: fwd chunk images ============
__global__ void wprep_k(const float* __restrict__ w12, const float* __restrict__ m12,
                        const float* __restrict__ m2,  const float* __restrict__ m3)
{
    int cb = blockIdx.x;
    const float* src; __nv_bfloat16* dst; int CIN, KK, c;
    if (cb<11){src=w12;dst=g_wb_w12;CIN=8;KK=81;c=cb;}
    else if (cb<22){src=m12;dst=g_wb_m12;CIN=8;KK=81;c=cb-11;}
    else if (cb<40){src=m2;dst=g_wb_m2;CIN=128;KK=9;c=cb-22;}
    else {src=m3;dst=g_wb_m3;CIN=128;KK=9;c=cb-40;}
    __nv_bfloat16* base = dst + c*16384;
    for (int e=threadIdx.x;e<8192;e+=256){
        int co=e>>6, kl=e&63, k=c*64+kl, tap=k/CIN, ci=k%CIN;
        float w = (tap<KK) ? src[(co*CIN+ci)*KK+tap] : 0.0f;
        u16 h,l; bfsplit(w,h,l);
        base[co*64+kl] = __ushort_as_bfloat16(h);
        base[8192 + co*64+kl] = __ushort_as_bfloat16(l);
    }
}

// ============ weight prep: adjoint fragment-ordered (flipped w1_2) ============
__global__ void wadjprep_k(const float* __restrict__ w12)
{
    int idx = blockIdx.x*256 + threadIdx.x;
    if (idx < 41472){
        int reg  = idx & 1;
        int lane = (idx>>1) & 31;
        int kk   = (idx>>6) & 7;
        int tap  = idx>>9;
        int n    = lane>>2;
        int k0   = (lane&3)*2 + reg*8;
        int c0   = kk*16 + k0, c1 = c0 + 1;
        float wa = w12[(c0*8 + n)*81 + (80 - tap)];
        float wb = w12[(c1*8 + n)*81 + (80 - tap)];
        u16 ha,la,hb,lb; bfsplit(wa,ha,la); bfsplit(wb,hb,lb);
        g_wadj_h[idx] = (u32)ha | ((u32)hb<<16);
        g_wadj_l[idx] = (u32)la | ((u32)lb<<16);
    }
}

// ---------------- scalar direct conv (small channel counts) ----------------
__device__ __forceinline__ u64 pack2(float a, float b){
    u64 r; asm("mov.b64 %0, {%1, %2};":"=l"(r):"f"(a),"f"(b)); return r;
}
__device__ __forceinline__ void unpack2(u64 v, float& a, float& b){
    asm("mov.b64 {%0, %1}, %2;":"=f"(a),"=f"(b):"l"(v));
}
__device__ __forceinline__ void fma2(u64& d, u64 a, u64 b){
    asm("fma.rn.f32x2 %0, %1, %2, %3;":"=l"(d):"l"(a),"l"(b),"l"(d));
}

// EPI: 0 = fp32 NCHW, 3 = BtB combine (COUT==1), 4 = bf16 hi/lo channel-last split
template<int KSZ, int CIN, int COUT, int CO_TILE, int OC, int TW, int CICH,
         bool TRANS, bool MUL, int EPI>
__global__ void __launch_bounds__(16*(TW/8)*(CO_TILE/OC))
conv_k(const float* __restrict__ in, const float* __restrict__ wgt,
       float* __restrict__ out, const float* __restrict__ mul,
       const float* __restrict__ xadd,
       __nv_bfloat16* __restrict__ bfh, __nv_bfloat16* __restrict__ bfl)
{
    constexpr int P=KSZ/2, KK=KSZ*KSZ, XG=TW/8, CG=CO_TILE/OC, NT=16*XG*CG;
    constexpr int R=16+KSZ-1, C=TW+KSZ-1, SC=C+1, NCH=CIN/CICH, WIN=8+KSZ-1;
    constexpr bool PACKED=((OC&1)==0);
    constexpr int O2=(OC+1)/2;

    extern __shared__ char s_raw[];
    float* smem = (float*)s_raw;
    float* s_in = smem;
    float* s_w  = s_in + CICH*R*SC;

    const int tid=threadIdx.x, cg=tid%CG, xg=(tid/CG)%XG, row=tid/(CG*XG);
    const int tx0=blockIdx.x*TW, ty0=blockIdx.y*16;
    const int b=blockIdx.z/(COUT/CO_TILE), coc=(blockIdx.z%(COUT/CO_TILE))*CO_TILE;

    float acc[8][OC]; u64 acc2[8][O2];
#pragma unroll
    for (int j=0;j<8;++j){
#pragma unroll
        for (int o=0;o<OC;++o) acc[j][o]=0.0f;
#pragma unroll
        for (int o=0;o<O2;++o) acc2[j][o]=0ull;
    }

#pragma unroll 1
    for (int ch=0; ch<NCH; ++ch){
        const int ci0 = ch*CICH;
        for (int i=tid;i<CICH*R*C;i+=NT){
            int ci=i/(R*C), rr=(i/C)%R, cc=i%C;
            int gy=ty0-P+rr, gx=tx0-P+cc;
            float v=0.0f;
            if (gy>=0&&gy<128&&gx>=0&&gx<128){
                int gi=((b*CIN+ci0+ci)*128+gy)*128+gx;
                v=in[gi]; if (MUL) v*=mul[gi];
            }
            s_in[(ci*R+rr)*SC+cc]=v;
        }
        for (int i=tid;i<CICH*KK*CO_TILE;i+=NT){
            int co=i%CO_TILE, tap=(i/CO_TILE)%KK, ci=i/(CO_TILE*KK);
            int gw = TRANS ? (((ci0+ci)*COUT+(coc+co))*KK+tap)
                           : (((coc+co)*CIN+(ci0+ci))*KK+tap);
            s_w[i]=wgt[gw];
        }
        __syncthreads();
#pragma unroll 1
        for (int ci=0;ci<CICH;++ci){
#pragma unroll 1
            for (int ky=0;ky<KSZ;++ky){
                const int rr = TRANS ? (row+(KSZ-1)-ky) : (row+ky);
                const float* rowp = &s_in[(ci*R+rr)*SC + xg*8];
                const float* wp = &s_w[(ci*KK+ky*KSZ)*CO_TILE + cg*OC];
                if (PACKED){
                    u64 win2[WIN];
#pragma unroll
                    for (int k=0;k<WIN;++k){ float v=rowp[k]; win2[k]=pack2(v,v); }
#pragma unroll
                    for (int kx=0;kx<KSZ;++kx){
                        u64 wv2[O2];
#pragma unroll
                        for (int o=0;o<O2;++o) wv2[o]=*(const u64*)(wp+kx*CO_TILE+2*o);
#pragma unroll
                        for (int j=0;j<8;++j){
                            const u64 iv2 = TRANS ? win2[j+(KSZ-1)-kx] : win2[j+kx];
#pragma unroll
                            for (int o=0;o<O2;++o) fma2(acc2[j][o], iv2, wv2[o]);
                        }
                    }
                } else {
                    float win[WIN];
#pragma unroll
                    for (int k=0;k<WIN;++k) win[k]=rowp[k];
#pragma unroll
                    for (int kx=0;kx<KSZ;++kx){
                        float wv[OC];
#pragma unroll
                        for (int o=0;o<OC;++o) wv[o]=wp[kx*CO_TILE+o];
#pragma unroll
                        for (int j=0;j<8;++j){
                            const float iv = TRANS ? win[j+(KSZ-1)-kx] : win[j+kx];
#pragma unroll
                            for (int o=0;o<OC;++o) acc[j][o]=fmaf(iv,wv[o],acc[j][o]);
                        }
                    }
                }
            }
        }
        __syncthreads();
    }
    if (PACKED){
#pragma unroll
        for (int j=0;j<8;++j)
#pragma unroll
            for (int o=0;o<O2;++o)
                unpack2(acc2[j][o], acc[j][2*o], acc[j][2*o+1<OC?2*o+1:0]);
    }
    const int y=ty0+row;
#pragma unroll
    for (int o=0;o<OC;++o){
        const int c=coc+cg*OC+o;
#pragma unroll
        for (int j=0;j<8;++j){
            const int xx=tx0+xg*8+j;
            float v=acc[j][o];
            if (EPI==4){
                u16 h,l; bfsplit(v,h,l);
                const int pix=(b*128+y)*128+xx;
                bfh[pix*COUT + c] = __ushort_as_bfloat16(h);
                bfl[pix*COUT + c] = __ushort_as_bfloat16(l);
            } else {
                if (EPI==3){
                    const int ii=(b*128+y)*128+xx;
                    v=(xadd[ii]+g_lam[b]*v)*g_inv1pl[b];
                }
                out[((b*COUT+c)*128+y)*128+xx]=v;
            }
        }
    }
}

// ---------------- small kernels ----------------
__global__ void setup_k(const float* __restrict__ sigma, const float* __restrict__ c_lam,
                        const float* __restrict__ c_scal)
{
    int t=threadIdx.x;
    if (t<NB){
        float l=spline_gen(c_lam,53,-1.0f,51.0f,sigma[t]);
        g_lam[t]=l; g_inv1pl[t]=1.0f/(1.0f+l);
    }
    for (int i=t;i<NB*128;i+=blockDim.x){
        int b=i>>7, c=i&127; float s=sigma[b];
        g_scaling[i]=expf(spline_gen(c_scal+c*14,14,-1.0f,51.0f,s))/(s+1e-5f);
    }
}
__global__ void init_k(float* __restrict__ x, const float* __restrict__ y){
    int i=blockIdx.x*blockDim.x+threadIdx.x;
    if (i<NB*NPIX){ x[i]=0.0f; g_b[i]=y[i]*g_inv1pl[i>>14]; }
}
// r = b - Bp; p = r; r^2 partials -> g_partB1
__global__ void resid_k(){
    __shared__ float red[256];
    int i=blockIdx.x*256+threadIdx.x;
    float r = g_b[i]-g_Bp[i];
    g_r[i]=r; g_p[i]=r;
    red[threadIdx.x]=r*r; __syncthreads();
    for (int st=128;st>0;st>>=1){ if (threadIdx.x<st) red[threadIdx.x]+=red[threadIdx.x+st]; __syncthreads(); }
    if (threadIdx.x==0) g_partB1[blockIdx.x]=red[0];
}
// 16-slice dot(p, Bp) -> g_partA
__global__ void dotpb_k(){
    __shared__ float red[256];
    int bslice=blockIdx.x;
    int base=(bslice>>4)*NPIX + (bslice&15)*1024;
    float s=0.0f;
#pragma unroll
    for (int j=0;j<4;++j){
        int idx=base+threadIdx.x+j*256;
        s=fmaf(g_p[idx],g_Bp[idx],s);
    }
    red[threadIdx.x]=s; __syncthreads();
    for (int st=128;st>0;st>>=1){ if (threadIdx.x<st) red[threadIdx.x]+=red[threadIdx.x+st]; __syncthreads(); }
    if (threadIdx.x==0) g_partA[bslice]=red[0];
}
// alpha inline; x += a p; r -= a Bp; new r^2 partials -> partNew
__global__ void updxr_k(float* __restrict__ x, const float* __restrict__ partOld,
                        float* __restrict__ partNew){
    __shared__ float red[256];
    int i=blockIdx.x*256+threadIdx.x;
    int b=i>>14;
    float rn=0.0f, den=0.0f;
#pragma unroll 1
    for (int j=0;j<64;++j) rn += partOld[b*64+j];
#pragma unroll 1
    for (int j=0;j<16;++j) den += g_partA[b*16+j];
    bool act = rn>1e-6f;
    float a = act ? rn/(act?den:1.0f) : 0.0f;
    x[i]=fmaf(a,g_p[i],x[i]);
    float r=fmaf(-a,g_Bp[i],g_r[i]);
    g_r[i]=r;
    red[threadIdx.x]=r*r; __syncthreads();
    for (int st=128;st>0;st>>=1){ if (threadIdx.x<st) red[threadIdx.x]+=red[threadIdx.x+st]; __syncthreads(); }
    if (threadIdx.x==0) partNew[blockIdx.x]=red[0];
}
// beta inline; p = r + beta p
__global__ void updp_k(const float* __restrict__ partOld, const float* __restrict__ partNew){
    int i=blockIdx.x*256+threadIdx.x;
    int b=i>>14;
    float rn=0.0f, rn2=0.0f;
#pragma unroll 1
    for (int j=0;j<64;++j){ rn += partOld[b*64+j]; rn2 += partNew[b*64+j]; }
    float beta=(rn>1e-6f)?rn2/rn:0.0f;
    g_p[i]=fmaf(beta,g_p[i],g_r[i]);
}

// ---------------- launch helpers ----------------
#define CONV(KSZ, CIN, COUT, COT, OC, TW, CICH, TR, MU, EPI, IN, W, OUT, MULP, XA, BH, BL) \
    do { \
        auto kfn = conv_k<KSZ, CIN, COUT, COT, OC, TW, CICH, TR, MU, EPI>; \
        constexpr int smb = ((CICH)*(16+(KSZ)-1)*((TW)+(KSZ)) + (CICH)*(KSZ)*(KSZ)*(COT) + 32)*4; \
        cudaFuncSetAttribute(kfn, cudaFuncAttributeMaxDynamicSharedMemorySize, smb); \
        dim3 gr(128/(TW), 8, NB*((COUT)/(COT))); \
        kfn<<<gr, 16*((TW)/8)*((COT)/(OC)), smb>>>(IN, W, OUT, MULP, XA, BH, BL); \
    } while (0)

extern "C" void kernel_launch(void* const* d_in, const int* in_sizes, int n_in_args,
                              void* d_out, int out_size)
{
    const float* y     = (const float*)d_in[0];
    const float* sigma = (const float*)d_in[1];
    const float* w1_0  = (const float*)d_in[2];
    const float* w1_1  = (const float*)d_in[3];
    const float* w1_2  = (const float*)d_in[4];
    const float* m1_0  = (const float*)d_in[5];
    const float* m1_1  = (const float*)d_in[6];
    const float* m1_2  = (const float*)d_in[7];
    const float* m2w   = (const float*)d_in[8];
    const float* m3w   = (const float*)d_in[9];
    const float* csp1  = (const float*)d_in[10];
    const float* csp2  = (const float*)d_in[11];
    const float* csp3  = (const float*)d_in[12];
    const float* clam  = (const float*)d_in[13];
    const float* cscal = (const float*)d_in[14];
    // n_out=2, n_in=6 fixed by setup_inputs (static loop counts for graph capture)

    float* x = (float*)d_out;

    float *t4,*t8,*msk2,*Bp,*pv,*pb1,*pb2;
    cudaGetSymbolAddress((void**)&t4,g_t4);
    cudaGetSymbolAddress((void**)&t8,g_t8);
    cudaGetSymbolAddress((void**)&msk2,g_mask2);
    cudaGetSymbolAddress((void**)&Bp,g_Bp);
    cudaGetSymbolAddress((void**)&pv,g_p);
    cudaGetSymbolAddress((void**)&pb1,g_partB1);
    cudaGetSymbolAddress((void**)&pb2,g_partB2);
    __nv_bfloat16 *t8h,*t8l,*ah,*al,*bh,*bl,*wbw,*wbm,*wb2,*wb3;
    cudaGetSymbolAddress((void**)&t8h,g_t8h);
    cudaGetSymbolAddress((void**)&t8l,g_t8l);
    cudaGetSymbolAddress((void**)&ah,g_ah);
    cudaGetSymbolAddress((void**)&al,g_al);
    cudaGetSymbolAddress((void**)&bh,g_bh);
    cudaGetSymbolAddress((void**)&bl,g_bl);
    cudaGetSymbolAddress((void**)&wbw,g_wb_w12);
    cudaGetSymbolAddress((void**)&wbm,g_wb_m12);
    cudaGetSymbolAddress((void**)&wb2,g_wb_m2);
    cudaGetSymbolAddress((void**)&wb3,g_wb_m3);

    const int EW_GRID = 512;

    wprep_k<<<58, 256>>>(w1_2, m1_2, m2w, m3w);
    wadjprep_k<<<162, 256>>>(w1_2);
    setup_k<<<1, 256>>>(sigma, clam, cscal);
    init_k<<<EW_GRID, 256>>>(x, y);

    auto tc9 = [&](int epi, const __nv_bfloat16* wbp, const float* spc, const float* mask){
        constexpr int smb = 16384 + 2*2*18432;   // 90112
        if (epi==1){
            cudaFuncSetAttribute(tconv9_k<1>, cudaFuncAttributeMaxDynamicSharedMemorySize, smb);
            tconv9_k<1><<<dim3(8,16,NB), 256, smb>>>(t8h, t8l, wbp, ah, al, spc, mask);
        } else {
            cudaFuncSetAttribute(tconv9_k<3>, cudaFuncAttributeMaxDynamicSharedMemorySize, smb);
            tconv9_k<3><<<dim3(8,16,NB), 256, smb>>>(t8h, t8l, wbp, ah, al, spc, mask);
        }
    };
    auto tc3 = [&](int epi, const __nv_bfloat16* ih, const __nv_bfloat16* il,
                   const __nv_bfloat16* wbp, float* of, __nv_bfloat16* oh, __nv_bfloat16* ol,
                   const float* spc){
        constexpr int smb = 1024 + 4*2*10240;    // 82944
        if (epi==1){
            cudaFuncSetAttribute(tconv3_k<1>, cudaFuncAttributeMaxDynamicSharedMemorySize, smb);
            tconv3_k<1><<<dim3(8,16,NB), 256, smb>>>(ih, il, wbp, of, oh, ol, spc);
        } else {
            cudaFuncSetAttribute(tconv3_k<2>, cudaFuncAttributeMaxDynamicSharedMemorySize, smb);
            tconv3_k<2><<<dim3(8,16,NB), 256, smb>>>(ih, il, wbp, of, oh, ol, spc);
        }
    };
    auto tadj = [&](){
        constexpr int smb = 384*272;             // 104448
        cudaFuncSetAttribute(tadj_k, cudaFuncAttributeMaxDynamicSharedMemorySize, smb);
        tadj_k<<<dim3(8,16,NB), 256, smb>>>(ah, al, t8);
    };

    // BtB(src)->dst
    auto btb = [&](const float* src, float* dst){
        CONV(9, 1, 4,   4, 1, 32, 1, false, false, 0, src, w1_0, t4, nullptr, nullptr, nullptr, nullptr);
        CONV(9, 4, 8,   8, 2, 16, 4, false, false, 4, t4,  w1_1, nullptr, nullptr, nullptr, t8h, t8l);
        tc9(3, wbw, nullptr, msk2);
        tadj();
        CONV(9, 8, 4,   4, 1, 16, 8, true, false, 0, t8,  w1_1, t4, nullptr, nullptr, nullptr, nullptr);
        CONV(9, 4, 1,   1, 1, 64, 4, true, false, 3, t4,  w1_0, dst, nullptr, src, nullptr, nullptr);
    };

    for (int outer=0; outer<N_OUT; ++outer){
        // cal_mask(x) -> g_mask2 (channel-last)
        CONV(9, 1, 4, 4, 1, 32, 1, false, false, 0, x,  m1_0, t4, nullptr, nullptr, nullptr, nullptr);
        CONV(9, 4, 8, 8, 2, 16, 4, false, false, 4, t4, m1_1, nullptr, nullptr, nullptr, t8h, t8l);
        tc9(1, wbm, csp1, nullptr);
        tc3(1, ah, al, wb2, nullptr, bh, bl, csp2);
        tc3(2, bh, bl, wb3, msk2, nullptr, nullptr, csp3);

        // CG init
        btb(x, Bp);
        resid_k<<<EW_GRID, 256>>>();

        for (int it=0; it<N_IN; ++it){
            float* oldp = (it&1) ? pb2 : pb1;
            float* newp = (it&1) ? pb1 : pb2;
            btb(pv, Bp);
            dotpb_k<<<NB*16, 256>>>();
            updxr_k<<<EW_GRID, 256>>>(x, oldp, newp);
            updp_k<<<EW_GRID, 256>>>(oldp, newp);
        }
    }
    (void)in_sizes; (void)n_in_args; (void)out_size;
}

// round 16
// speedup vs baseline: 1.3957x; 1.3957x over previous
#include <cuda_runtime.h>
#include <cuda_bf16.h>
#include <math.h>

#define NB 8
#define NPIX 16384
#define N_OUT 2
#define N_IN 6
typedef unsigned long long u64;
typedef unsigned int u32;
typedef unsigned short u16;

// ---------------- scratch (static device globals) ----------------
__device__ float g_t4[NB*4*NPIX];
__device__ float g_t8[NB*8*NPIX];
__device__ float g_mask2[NB*NPIX*128];          // channel-last [b][pix][128]
__device__ float g_b[NB*NPIX], g_r[NB*NPIX], g_p[NB*NPIX], g_Bp[NB*NPIX];
// channel-last bf16 hi/lo planes
__device__ __nv_bfloat16 g_t8h[NB*NPIX*8], g_t8l[NB*NPIX*8];
__device__ __nv_bfloat16 g_ah[NB*NPIX*128], g_al[NB*NPIX*128];
__device__ __nv_bfloat16 g_bh[NB*NPIX*128], g_bl[NB*NPIX*128];
// bf16 weight images for tconv: per chunk [hi 128x64][lo 128x64] row-major
__device__ __nv_bfloat16 g_wb_w12[11*2*8192], g_wb_m12[11*2*8192];
__device__ __nv_bfloat16 g_wb_m2 [18*2*8192], g_wb_m3 [18*2*8192];
// fragment-ordered adjoint weights: [81 tap][8 k16][32 lane][2 reg] u32
__device__ u32 g_wadj_h[41472], g_wadj_l[41472];
__device__ float g_lam[NB], g_inv1pl[NB], g_scaling[NB*128];
__device__ float g_partA[NB*16], g_partB1[NB*64], g_partB2[NB*64];

// ---------------- PTX helpers (baseline PTX only) ----------------
__device__ __forceinline__ u32 smem_u32(const void* p){
    u32 a; asm("{ .reg .u64 t; cvta.to.shared.u64 t, %1; cvt.u32.u64 %0, t; }":"=r"(a):"l"(p)); return a;
}
__device__ __forceinline__ void cp16(u32 dst, const void* src, bool pred){
    int sz = pred ? 16 : 0;
    asm volatile("cp.async.ca.shared.global [%0], [%1], 16, %2;"
                 :: "r"(dst), "l"(src), "r"(sz) : "memory");
}
__device__ __forceinline__ void cp_commit(){ asm volatile("cp.async.commit_group;":::"memory"); }
template<int N> __device__ __forceinline__ void cp_wait(){
    asm volatile("cp.async.wait_group %0;"::"n"(N):"memory");
}
__device__ __forceinline__ void ldsm4(u32* r, u32 addr){
    asm volatile("ldmatrix.sync.aligned.m8n8.x4.shared.b16 {%0,%1,%2,%3}, [%4];"
                 : "=r"(r[0]),"=r"(r[1]),"=r"(r[2]),"=r"(r[3]) : "r"(addr));
}
__device__ __forceinline__ void mma_bf16(float* c, const u32* a, const u32* b){
    asm volatile("mma.sync.aligned.m16n8k16.row.col.f32.bf16.bf16.f32 "
                 "{%0,%1,%2,%3}, {%4,%5,%6,%7}, {%8,%9}, {%0,%1,%2,%3};"
                 : "+f"(c[0]),"+f"(c[1]),"+f"(c[2]),"+f"(c[3])
                 : "r"(a[0]),"r"(a[1]),"r"(a[2]),"r"(a[3]), "r"(b[0]),"r"(b[1]));
}

// ---------------- splines / split ----------------
__device__ __forceinline__ float spline_gen(const float* __restrict__ c, int K,
                                            float xmin, float xmax, float x){
    float step=(xmax-xmin)/(float)(K-1);
    float t=(x-xmin)/step, f=floorf(t);
    f=fminf(fmaxf(f,0.0f),(float)(K-2));
    int i=(int)f; float fr=t-f;
    return fmaf(fr, c[i+1]-c[i], c[i]);
}
__device__ __forceinline__ float spline31(const float* __restrict__ c, float v){
    float t=v*10.0f, f=floorf(t);
    f=fminf(fmaxf(f,0.0f),29.0f);
    int i=(int)f; float fr=t-f;
    return fmaf(fr, c[i+1]-c[i], c[i]);
}
__device__ __forceinline__ void bfsplit(float v, u16& h, u16& l){
    __nv_bfloat16 hb=__float2bfloat16_rn(v);
    h=__bfloat16_as_ushort(hb);
    l=__bfloat16_as_ushort(__float2bfloat16_rn(v-__bfloat162float(hb)));
}

// ============ 9x9 CIN=8 fwd tconv: resident halo A, double-buffered B ============
// EPI: 1 = spline31(|v|) -> bf16 hi/lo channel-last,
//      3 = multiply by mask2 (channel-last fp32) -> bf16 hi/lo channel-last
template<int EPI>
__global__ void __launch_bounds__(256)
tconv9_k(const __nv_bfloat16* __restrict__ inh, const __nv_bfloat16* __restrict__ inl,
         const __nv_bfloat16* __restrict__ wb,
         __nv_bfloat16* __restrict__ outh, __nv_bfloat16* __restrict__ outl,
         const float* __restrict__ spc, const float* __restrict__ maskp)
{
    constexpr int HALO = 1024;
    constexpr int BB   = 16384;
    constexpr int BPL  = 18432;
    constexpr int BBUF = 2*BPL;

    extern __shared__ char s_raw[];
    const u32 sb = smem_u32(s_raw);
    float* hdr = (float*)s_raw;
    const int tid = threadIdx.x, wid = tid>>5, lid = tid&31;
    const int x0 = blockIdx.x*16, y0 = blockIdx.y*8, b = blockIdx.z;

    if (EPI==1 && tid<31) hdr[tid] = spc[tid];

    for (int i=tid; i<768; i+=256){
        int pl = (i>=384), px = i - pl*384;
        int iy = px/24, ix = px - iy*24;
        int gy = y0+iy-4, gx = x0+ix-4;
        bool ok = ((u32)gy<128u) && ((u32)gx<128u);
        const __nv_bfloat16* srcb = pl ? inl : inh;
        const void* src = ok ? (const void*)(srcb + ((b*128+gy)*128+gx)*8) : (const void*)srcb;
        cp16(sb + HALO + (u32)(pl*6400 + iy*400 + ix*16), src, ok);
    }
    auto stageB = [&](int c, int buf){
#pragma unroll
        for (int it=0; it<8; ++it){
            int idx = tid + it*256;
            int pl = idx>>10, r = idx&1023;
            int n = r>>3, s = r&7;
            const __nv_bfloat16* src = wb + c*16384 + pl*8192 + n*64 + s*8;
            cp16(sb + BB + (u32)(buf*BBUF + pl*BPL + n*144 + s*16), src, true);
        }
        cp_commit();
    };

    float acc[8][2][4];
#pragma unroll
    for (int i=0;i<8;++i)
#pragma unroll
        for (int j=0;j<2;++j)
#pragma unroll
            for (int k=0;k<4;++k) acc[i][j][k]=0.0f;

    const int rr = lid & 7, t = lid >> 3;
    const int mx = rr + (t&1)*8;
    const u32 bOff = (u32)((wid*16 + (t>>1)*8 + rr)*144 + (t&1)*16);

    stageB(0, 0);
#pragma unroll 1
    for (int c=0; c<11; ++c){
        const int buf = c&1;
        if (c+1 < 11){ stageB(c+1, buf^1); cp_wait<1>(); }
        else         { cp_wait<0>(); }
        __syncthreads();

        const u32 bH = sb + BB + buf*BBUF, bL = bH + BPL;
#pragma unroll
        for (int k16=0; k16<4; ++k16){
            u32 bh[4], bl[4];
            ldsm4(bh, bH + bOff + k16*32);
            ldsm4(bl, bL + bOff + k16*32);
            int ta = c*8 + k16*2, tb = ta + 1;
            if (ta>80) ta=80;
            if (tb>80) tb=80;
            int tap = (t>>1) ? tb : ta;
            int ky = tap/9, kx = tap - ky*9;
            const u32 aBase = sb + HALO + (u32)(ky*400 + (mx + kx)*16);
#pragma unroll
            for (int mt=0; mt<8; ++mt){
                u32 ah[4], al[4];
                ldsm4(ah, aBase + (u32)(mt*400));
                ldsm4(al, aBase + (u32)(mt*400) + 6400u);
                mma_bf16(acc[mt][0], ah, bh+0);
                mma_bf16(acc[mt][1], ah, bh+2);
                mma_bf16(acc[mt][0], al, bh+0);
                mma_bf16(acc[mt][1], al, bh+2);
                mma_bf16(acc[mt][0], ah, bl+0);
                mma_bf16(acc[mt][1], ah, bl+2);
            }
        }
        __syncthreads();
    }

    const int row = lid>>2, q = (lid&3)*2;
#pragma unroll
    for (int mt=0; mt<8; ++mt){
        const int gy = y0 + mt;
        const int gxa = x0 + row, gxb = gxa + 8;
#pragma unroll
        for (int nt=0; nt<2; ++nt){
            const int n = wid*16 + nt*8 + q;
            const int pa = (b*128+gy)*128+gxa, pb = (b*128+gy)*128+gxb;
            float v0 = acc[mt][nt][0], v1 = acc[mt][nt][1];
            float v2 = acc[mt][nt][2], v3 = acc[mt][nt][3];
            if (EPI==1){
                v0 = spline31(hdr, fabsf(v0)); v1 = spline31(hdr, fabsf(v1));
                v2 = spline31(hdr, fabsf(v2)); v3 = spline31(hdr, fabsf(v3));
            } else {
                float2 m0 = *(const float2*)(maskp + (long)pa*128 + n);
                float2 m1 = *(const float2*)(maskp + (long)pb*128 + n);
                v0 *= m0.x; v1 *= m0.y;
                v2 *= m1.x; v3 *= m1.y;
            }
            u16 h0,l0,h1,l1,h2,l2,h3,l3;
            bfsplit(v0,h0,l0); bfsplit(v1,h1,l1);
            bfsplit(v2,h2,l2); bfsplit(v3,h3,l3);
            *(u32*)(outh + (long)pa*128 + n) = (u32)h0 | ((u32)h1<<16);
            *(u32*)(outl + (long)pa*128 + n) = (u32)l0 | ((u32)l1<<16);
            *(u32*)(outh + (long)pb*128 + n) = (u32)h2 | ((u32)h3<<16);
            *(u32*)(outl + (long)pb*128 + n) = (u32)l2 | ((u32)l3<<16);
        }
    }
}

// ============ 3x3 CIN=128 tconv: 32-k chunks (pitch 80) ============
// EPI: 1 = spline31(|v|)->bf16 hi/lo channel-last, 2 = mask final -> fp32 channel-last
template<int EPI>
__global__ void __launch_bounds__(256)
tconv3_k(const __nv_bfloat16* __restrict__ inh, const __nv_bfloat16* __restrict__ inl,
         const __nv_bfloat16* __restrict__ wb, float* __restrict__ outf,
         __nv_bfloat16* __restrict__ outh, __nv_bfloat16* __restrict__ outl,
         const float* __restrict__ spc)
{
    constexpr int NKC   = 36;
    constexpr int HDR   = 1024;
    constexpr int PLANE = 128*80;
    constexpr int BUF   = 2*PLANE;
    constexpr int SM_A  = HDR;
    constexpr int SM_B  = HDR + 2*BUF;

    extern __shared__ char s_raw[];
    const u32 sb = smem_u32(s_raw);
    float* hdr = (float*)s_raw;
    const int tid = threadIdx.x, wid = tid>>5, lid = tid&31;
    const int x0 = blockIdx.x*16, y0 = blockIdx.y*8, b = blockIdx.z;

    if (tid<31) hdr[tid] = spc[tid];
    if (EPI==2 && tid>=64 && tid<192) hdr[32+tid-64] = g_scaling[b*128+tid-64];

    auto stage = [&](int c, int buf){
        const int tap = c>>2, q = c&3;
        const int ky = tap/3, kx = tap%3;
        const int c64 = c>>1, h = c&1;
#pragma unroll
        for (int it=0; it<4; ++it){
            int idx = tid + it*256;
            int pl = idx>>9, r = idx&511;
            int m = r>>2, s = r&3;
            int my = m>>4, mxx = m&15;
            const __nv_bfloat16* srcb = pl ? inl : inh;
            const void* src = srcb; bool ok = false;
            int gy = y0+my+ky-1, gx = x0+mxx+kx-1;
            if ((u32)gy<128u && (u32)gx<128u){
                ok = true; src = srcb + ((b*128+gy)*128+gx)*128 + q*32 + s*8;
            }
            cp16(sb + SM_A + buf*BUF + pl*PLANE + m*80 + s*16, src, ok);
        }
#pragma unroll
        for (int it=0; it<4; ++it){
            int idx = tid + it*256;
            int pl = idx>>9, r = idx&511;
            int n = r>>2, s = r&3;
            const __nv_bfloat16* src = wb + c64*16384 + pl*8192 + n*64 + h*32 + s*8;
            cp16(sb + SM_B + buf*BUF + pl*PLANE + n*80 + s*16, src, true);
        }
        cp_commit();
    };

    float acc[8][2][4];
#pragma unroll
    for (int i=0;i<8;++i)
#pragma unroll
        for (int j=0;j<2;++j)
#pragma unroll
            for (int k=0;k<4;++k) acc[i][j][k]=0.0f;

    const int rr = lid & 7, t = lid >> 3;
    const u32 aOff = (u32)((rr + (t&1)*8)*80 + (t>>1)*16);
    const u32 bOff = (u32)((wid*16 + (t>>1)*8 + rr)*80 + (t&1)*16);

    stage(0, 0);
#pragma unroll 1
    for (int c=0; c<NKC; ++c){
        const int buf = c&1;
        if (c+1 < NKC){ stage(c+1, buf^1); cp_wait<1>(); }
        else          { cp_wait<0>(); }
        __syncthreads();

        const u32 aH = sb + SM_A + buf*BUF, aL = aH + PLANE;
        const u32 bH = sb + SM_B + buf*BUF, bL = bH + PLANE;
#pragma unroll
        for (int k16=0; k16<2; ++k16){
            u32 bh[4], bl[4];
            ldsm4(bh, bH + bOff + k16*32);
            ldsm4(bl, bL + bOff + k16*32);
#pragma unroll
            for (int mt=0; mt<8; ++mt){
                u32 ah[4], al[4];
                ldsm4(ah, aH + aOff + mt*1280 + k16*32);
                ldsm4(al, aL + aOff + mt*1280 + k16*32);
                mma_bf16(acc[mt][0], ah, bh+0);
                mma_bf16(acc[mt][1], ah, bh+2);
                mma_bf16(acc[mt][0], al, bh+0);
                mma_bf16(acc[mt][1], al, bh+2);
                mma_bf16(acc[mt][0], ah, bl+0);
                mma_bf16(acc[mt][1], ah, bl+2);
            }
        }
        __syncthreads();
    }

    const int row = lid>>2, q = (lid&3)*2;
#pragma unroll
    for (int mt=0; mt<8; ++mt){
        const int gy = y0 + mt;
        const int gxa = x0 + row, gxb = gxa + 8;
#pragma unroll
        for (int nt=0; nt<2; ++nt){
            const int n = wid*16 + nt*8 + q;
            const int pa = (b*128+gy)*128+gxa, pb = (b*128+gy)*128+gxb;
            float v0 = acc[mt][nt][0], v1 = acc[mt][nt][1];
            float v2 = acc[mt][nt][2], v3 = acc[mt][nt][3];
            if (EPI==1){
                v0 = spline31(hdr, fabsf(v0)); v1 = spline31(hdr, fabsf(v1));
                v2 = spline31(hdr, fabsf(v2)); v3 = spline31(hdr, fabsf(v3));
                u16 h0,l0,h1,l1,h2,l2,h3,l3;
                bfsplit(v0,h0,l0); bfsplit(v1,h1,l1);
                bfsplit(v2,h2,l2); bfsplit(v3,h3,l3);
                *(u32*)(outh + (long)pa*128 + n) = (u32)h0 | ((u32)h1<<16);
                *(u32*)(outl + (long)pa*128 + n) = (u32)l0 | ((u32)l1<<16);
                *(u32*)(outh + (long)pb*128 + n) = (u32)h2 | ((u32)h3<<16);
                *(u32*)(outl + (long)pb*128 + n) = (u32)l2 | ((u32)l3<<16);
            } else {
                float s0 = hdr[32+n], s1 = hdr[32+n+1];
                v0 = spline31(hdr, s0*fabsf(v0)); v0 = fminf(fmaxf(v0,0.01f),1.0f); v0 *= v0;
                v1 = spline31(hdr, s1*fabsf(v1)); v1 = fminf(fmaxf(v1,0.01f),1.0f); v1 *= v1;
                v2 = spline31(hdr, s0*fabsf(v2)); v2 = fminf(fmaxf(v2,0.01f),1.0f); v2 *= v2;
                v3 = spline31(hdr, s1*fabsf(v3)); v3 = fminf(fmaxf(v3,0.01f),1.0f); v3 *= v3;
                float2 w0v; w0v.x=v0; w0v.y=v1;
                float2 w1v; w1v.x=v2; w1v.y=v3;
                *(float2*)(outf + (long)pa*128 + n) = w0v;
                *(float2*)(outf + (long)pb*128 + n) = w1v;
            }
        }
    }
}

// ============ adjoint conv 128->8 via mma.sync, ci split in 2 halves ============
// R16: minimal chain-split — 3 accumulators (one per split term), no prefetch.
// (R15's 6-acc + prefetch variant spilled and regressed; this adds only +8 regs.)
__global__ void __launch_bounds__(256)
tadj_k(const __nv_bfloat16* __restrict__ mh, const __nv_bfloat16* __restrict__ ml,
       float* __restrict__ out8)
{
    extern __shared__ char s_raw[];
    const u32 sb = smem_u32(s_raw);
    const int tid = threadIdx.x, wid = tid>>5, lid = tid&31;
    const int x0 = blockIdx.x*16, y0 = blockIdx.y*8, b = blockIdx.z;

    float a0[4]={0,0,0,0}, a1[4]={0,0,0,0}, a2[4]={0,0,0,0};
    const int rr = lid&7, t = lid>>3;
    const int rowSel = rr + (t&1)*8;
    const u32 colSel = (u32)((t>>1)*16);

    const uint2* __restrict__ whv = (const uint2*)g_wadj_h;
    const uint2* __restrict__ wlv = (const uint2*)g_wadj_l;

#pragma unroll 1
    for (int h=0; h<2; ++h){
        for (int i=tid; i<6144; i+=256){
            int px = i>>4, r = i&15, pl = r>>3, seg = r&7;
            int iy = px/24, ix = px - iy*24;
            int gy = y0+iy-4, gx = x0+ix-4;
            bool ok = ((u32)gy<128u) && ((u32)gx<128u);
            const __nv_bfloat16* srcb = pl ? ml : mh;
            const void* src = ok ? (const void*)(srcb + (((long)(b*128+gy)*128+gx)*128 + h*64 + seg*8))
                                 : (const void*)srcb;
            cp16(sb + (u32)(px*272 + pl*128 + seg*16), src, ok);
        }
        cp_commit(); cp_wait<0>();
        __syncthreads();

#pragma unroll 1
        for (int tap=0; tap<81; ++tap){
            int ky = tap/9, kx = tap - ky*9;
            const u32 base = sb + (u32)(((wid+ky)*24 + rowSel + kx)*272) + colSel;
            const uint2* bh = whv + tap*256 + h*128 + lid;
            const uint2* bl = wlv + tap*256 + h*128 + lid;
#pragma unroll
            for (int kk=0; kk<4; ++kk){
                u32 ah[4], al[4];
                ldsm4(ah, base + kk*32);
                ldsm4(al, base + 128 + kk*32);
                uint2 vh = __ldg(bh + kk*32);
                uint2 vl = __ldg(bl + kk*32);
                mma_bf16(a0, ah, (const u32*)&vh);
                mma_bf16(a1, al, (const u32*)&vh);
                mma_bf16(a2, ah, (const u32*)&vl);
            }
        }
        __syncthreads();
    }

    const int xr = lid>>2, co = (lid&3)*2;
    const int gy = y0 + wid;
    float* o0 = out8 + ((b*8+co)*128 + gy)*128 + x0;
    float* o1 = o0 + NPIX;
    o0[xr]   = (a0[0]+a1[0])+a2[0];
    o1[xr]   = (a0[1]+a1[1])+a2[1];
    o0[xr+8] = (a0[2]+a1[2])+a2[2];
    o1[xr+8] = (a0[3]+a1[3])+a2[3];
}

// ============ weight prep: fwd chunk images ============
__global__ void wprep_k(const float* __restrict__ w12, const float* __restrict__ m12,
                        const float* __restrict__ m2,  const float* __restrict__ m3)
{
    int cb = blockIdx.x;
    const float* src; __nv_bfloat16* dst; int CIN, KK, c;
    if (cb<11){src=w12;dst=g_wb_w12;CIN=8;KK=81;c=cb;}
    else if (cb<22){src=m12;dst=g_wb_m12;CIN=8;KK=81;c=cb-11;}
    else if (cb<40){src=m2;dst=g_wb_m2;CIN=128;KK=9;c=cb-22;}
    else {src=m3;dst=g_wb_m3;CIN=128;KK=9;c=cb-40;}
    __nv_bfloat16* base = dst + c*16384;
    for (int e=threadIdx.x;e<8192;e+=256){
        int co=e>>6, kl=e&63, k=c*64+kl, tap=k/CIN, ci=k%CIN;
        float w = (tap<KK) ? src[(co*CIN+ci)*KK+tap] : 0.0f;
        u16 h,l; bfsplit(w,h,l);
        base[co*64+kl] = __ushort_as_bfloat16(h);
        base[8192 + co*64+kl] = __ushort_as_bfloat16(l);
    }
}

// ============ weight prep: adjoint fragment-ordered (flipped w1_2) ============
__global__ void wadjprep_k(const float* __restrict__ w12)
{
    int idx = blockIdx.x*256 + threadIdx.x;
    if (idx < 41472){
        int reg  = idx & 1;
        int lane = (idx>>1) & 31;
        int kk   = (idx>>6) & 7;
        int tap  = idx>>9;
        int n    = lane>>2;
        int k0   = (lane&3)*2 + reg*8;
        int c0   = kk*16 + k0, c1 = c0 + 1;
        float wa = w12[(c0*8 + n)*81 + (80 - tap)];
        float wb = w12[(c1*8 + n)*81 + (80 - tap)];
        u16 ha,la,hb,lb; bfsplit(wa,ha,la); bfsplit(wb,hb,lb);
        g_wadj_h[idx] = (u32)ha | ((u32)hb<<16);
        g_wadj_l[idx] = (u32)la | ((u32)lb<<16);
    }
}

// ---------------- scalar direct conv (small channel counts) ----------------
__device__ __forceinline__ u64 pack2(float a, float b){
    u64 r; asm("mov.b64 %0, {%1, %2};":"=l"(r):"f"(a),"f"(b)); return r;
}
__device__ __forceinline__ void unpack2(u64 v, float& a, float& b){
    asm("mov.b64 {%0, %1}, %2;":"=f"(a),"=f"(b):"l"(v));
}
__device__ __forceinline__ void fma2(u64& d, u64 a, u64 b){
    asm("fma.rn.f32x2 %0, %1, %2, %3;":"=l"(d):"l"(a),"l"(b),"l"(d));
}

// EPI: 0 = fp32 NCHW, 3 = BtB combine (COUT==1), 4 = bf16 hi/lo channel-last split
template<int KSZ, int CIN, int COUT, int CO_TILE, int OC, int TW, int CICH,
         bool TRANS, bool MUL, int EPI>
__global__ void __launch_bounds__(16*(TW/8)*(CO_TILE/OC))
conv_k(const float* __restrict__ in, const float* __restrict__ wgt,
       float* __restrict__ out, const float* __restrict__ mul,
       const float* __restrict__ xadd,
       __nv_bfloat16* __restrict__ bfh, __nv_bfloat16* __restrict__ bfl)
{
    constexpr int P=KSZ/2, KK=KSZ*KSZ, XG=TW/8, CG=CO_TILE/OC, NT=16*XG*CG;
    constexpr int R=16+KSZ-1, C=TW+KSZ-1, SC=C+1, NCH=CIN/CICH, WIN=8+KSZ-1;
    constexpr bool PACKED=((OC&1)==0);
    constexpr int O2=(OC+1)/2;

    extern __shared__ char s_raw[];
    float* smem = (float*)s_raw;
    float* s_in = smem;
    float* s_w  = s_in + CICH*R*SC;

    const int tid=threadIdx.x, cg=tid%CG, xg=(tid/CG)%XG, row=tid/(CG*XG);
    const int tx0=blockIdx.x*TW, ty0=blockIdx.y*16;
    const int b=blockIdx.z/(COUT/CO_TILE), coc=(blockIdx.z%(COUT/CO_TILE))*CO_TILE;

    float acc[8][OC]; u64 acc2[8][O2];
#pragma unroll
    for (int j=0;j<8;++j){
#pragma unroll
        for (int o=0;o<OC;++o) acc[j][o]=0.0f;
#pragma unroll
        for (int o=0;o<O2;++o) acc2[j][o]=0ull;
    }

#pragma unroll 1
    for (int ch=0; ch<NCH; ++ch){
        const int ci0 = ch*CICH;
        for (int i=tid;i<CICH*R*C;i+=NT){
            int ci=i/(R*C), rr=(i/C)%R, cc=i%C;
            int gy=ty0-P+rr, gx=tx0-P+cc;
            float v=0.0f;
            if (gy>=0&&gy<128&&gx>=0&&gx<128){
                int gi=((b*CIN+ci0+ci)*128+gy)*128+gx;
                v=in[gi]; if (MUL) v*=mul[gi];
            }
            s_in[(ci*R+rr)*SC+cc]=v;
        }
        for (int i=tid;i<CICH*KK*CO_TILE;i+=NT){
            int co=i%CO_TILE, tap=(i/CO_TILE)%KK, ci=i/(CO_TILE*KK);
            int gw = TRANS ? (((ci0+ci)*COUT+(coc+co))*KK+tap)
                           : (((coc+co)*CIN+(ci0+ci))*KK+tap);
            s_w[i]=wgt[gw];
        }
        __syncthreads();
#pragma unroll 1
        for (int ci=0;ci<CICH;++ci){
#pragma unroll 1
            for (int ky=0;ky<KSZ;++ky){
                const int rr = TRANS ? (row+(KSZ-1)-ky) : (row+ky);
                const float* rowp = &s_in[(ci*R+rr)*SC + xg*8];
                const float* wp = &s_w[(ci*KK+ky*KSZ)*CO_TILE + cg*OC];
                if (PACKED){
                    u64 win2[WIN];
#pragma unroll
                    for (int k=0;k<WIN;++k){ float v=rowp[k]; win2[k]=pack2(v,v); }
#pragma unroll
                    for (int kx=0;kx<KSZ;++kx){
                        u64 wv2[O2];
#pragma unroll
                        for (int o=0;o<O2;++o) wv2[o]=*(const u64*)(wp+kx*CO_TILE+2*o);
#pragma unroll
                        for (int j=0;j<8;++j){
                            const u64 iv2 = TRANS ? win2[j+(KSZ-1)-kx] : win2[j+kx];
#pragma unroll
                            for (int o=0;o<O2;++o) fma2(acc2[j][o], iv2, wv2[o]);
                        }
                    }
                } else {
                    float win[WIN];
#pragma unroll
                    for (int k=0;k<WIN;++k) win[k]=rowp[k];
#pragma unroll
                    for (int kx=0;kx<KSZ;++kx){
                        float wv[OC];
#pragma unroll
                        for (int o=0;o<OC;++o) wv[o]=wp[kx*CO_TILE+o];
#pragma unroll
                        for (int j=0;j<8;++j){
                            const float iv = TRANS ? win[j+(KSZ-1)-kx] : win[j+kx];
#pragma unroll
                            for (int o=0;o<OC;++o) acc[j][o]=fmaf(iv,wv[o],acc[j][o]);
                        }
                    }
                }
            }
        }
        __syncthreads();
    }
    if (PACKED){
#pragma unroll
        for (int j=0;j<8;++j)
#pragma unroll
            for (int o=0;o<O2;++o)
                unpack2(acc2[j][o], acc[j][2*o], acc[j][2*o+1<OC?2*o+1:0]);
    }
    const int y=ty0+row;
#pragma unroll
    for (int o=0;o<OC;++o){
        const int c=coc+cg*OC+o;
#pragma unroll
        for (int j=0;j<8;++j){
            const int xx=tx0+xg*8+j;
            float v=acc[j][o];
            if (EPI==4){
                u16 h,l; bfsplit(v,h,l);
                const int pix=(b*128+y)*128+xx;
                bfh[pix*COUT + c] = __ushort_as_bfloat16(h);
                bfl[pix*COUT + c] = __ushort_as_bfloat16(l);
            } else {
                if (EPI==3){
                    const int ii=(b*128+y)*128+xx;
                    v=(xadd[ii]+g_lam[b]*v)*g_inv1pl[b];
                }
                out[((b*COUT+c)*128+y)*128+xx]=v;
            }
        }
    }
}

// ---------------- small kernels ----------------
__global__ void setup_k(const float* __restrict__ sigma, const float* __restrict__ c_lam,
                        const float* __restrict__ c_scal)
{
    int t=threadIdx.x;
    if (t<NB){
        float l=spline_gen(c_lam,53,-1.0f,51.0f,sigma[t]);
        g_lam[t]=l; g_inv1pl[t]=1.0f/(1.0f+l);
    }
    for (int i=t;i<NB*128;i+=blockDim.x){
        int b=i>>7, c=i&127; float s=sigma[b];
        g_scaling[i]=expf(spline_gen(c_scal+c*14,14,-1.0f,51.0f,s))/(s+1e-5f);
    }
}
__global__ void init_k(float* __restrict__ x, const float* __restrict__ y){
    int i=blockIdx.x*blockDim.x+threadIdx.x;
    if (i<NB*NPIX){ x[i]=0.0f; g_b[i]=y[i]*g_inv1pl[i>>14]; }
}
// r = b - Bp; p = r; r^2 partials -> g_partB1
__global__ void resid_k(){
    __shared__ float red[256];
    int i=blockIdx.x*256+threadIdx.x;
    float r = g_b[i]-g_Bp[i];
    g_r[i]=r; g_p[i]=r;
    red[threadIdx.x]=r*r; __syncthreads();
    for (int st=128;st>0;st>>=1){ if (threadIdx.x<st) red[threadIdx.x]+=red[threadIdx.x+st]; __syncthreads(); }
    if (threadIdx.x==0) g_partB1[blockIdx.x]=red[0];
}
// 16-slice dot(p, Bp) -> g_partA
__global__ void dotpb_k(){
    __shared__ float red[256];
    int bslice=blockIdx.x;
    int base=(bslice>>4)*NPIX + (bslice&15)*1024;
    float s=0.0f;
#pragma unroll
    for (int j=0;j<4;++j){
        int idx=base+threadIdx.x+j*256;
        s=fmaf(g_p[idx],g_Bp[idx],s);
    }
    red[threadIdx.x]=s; __syncthreads();
    for (int st=128;st>0;st>>=1){ if (threadIdx.x<st) red[threadIdx.x]+=red[threadIdx.x+st]; __syncthreads(); }
    if (threadIdx.x==0) g_partA[bslice]=red[0];
}
// alpha inline; x += a p; r -= a Bp; new r^2 partials -> partNew
__global__ void updxr_k(float* __restrict__ x, const float* __restrict__ partOld,
                        float* __restrict__ partNew){
    __shared__ float red[256];
    int i=blockIdx.x*256+threadIdx.x;
    int b=i>>14;
    float rn=0.0f, den=0.0f;
#pragma unroll 1
    for (int j=0;j<64;++j) rn += partOld[b*64+j];
#pragma unroll 1
    for (int j=0;j<16;++j) den += g_partA[b*16+j];
    bool act = rn>1e-6f;
    float a = act ? rn/(act?den:1.0f) : 0.0f;
    x[i]=fmaf(a,g_p[i],x[i]);
    float r=fmaf(-a,g_Bp[i],g_r[i]);
    g_r[i]=r;
    red[threadIdx.x]=r*r; __syncthreads();
    for (int st=128;st>0;st>>=1){ if (threadIdx.x<st) red[threadIdx.x]+=red[threadIdx.x+st]; __syncthreads(); }
    if (threadIdx.x==0) partNew[blockIdx.x]=red[0];
}
// beta inline; p = r + beta p
__global__ void updp_k(const float* __restrict__ partOld, const float* __restrict__ partNew){
    int i=blockIdx.x*256+threadIdx.x;
    int b=i>>14;
    float rn=0.0f, rn2=0.0f;
#pragma unroll 1
    for (int j=0;j<64;++j){ rn += partOld[b*64+j]; rn2 += partNew[b*64+j]; }
    float beta=(rn>1e-6f)?rn2/rn:0.0f;
    g_p[i]=fmaf(beta,g_p[i],g_r[i]);
}

// ---------------- launch helpers ----------------
#define CONV(KSZ, CIN, COUT, COT, OC, TW, CICH, TR, MU, EPI, IN, W, OUT, MULP, XA, BH, BL) \
    do { \
        auto kfn = conv_k<KSZ, CIN, COUT, COT, OC, TW, CICH, TR, MU, EPI>; \
        constexpr int smb = ((CICH)*(16+(KSZ)-1)*((TW)+(KSZ)) + (CICH)*(KSZ)*(KSZ)*(COT) + 32)*4; \
        cudaFuncSetAttribute(kfn, cudaFuncAttributeMaxDynamicSharedMemorySize, smb); \
        dim3 gr(128/(TW), 8, NB*((COUT)/(COT))); \
        kfn<<<gr, 16*((TW)/8)*((COT)/(OC)), smb>>>(IN, W, OUT, MULP, XA, BH, BL); \
    } while (0)

extern "C" void kernel_launch(void* const* d_in, const int* in_sizes, int n_in_args,
                              void* d_out, int out_size)
{
    const float* y     = (const float*)d_in[0];
    const float* sigma = (const float*)d_in[1];
    const float* w1_0  = (const float*)d_in[2];
    const float* w1_1  = (const float*)d_in[3];
    const float* w1_2  = (const float*)d_in[4];
    const float* m1_0  = (const float*)d_in[5];
    const float* m1_1  = (const float*)d_in[6];
    const float* m1_2  = (const float*)d_in[7];
    const float* m2w   = (const float*)d_in[8];
    const float* m3w   = (const float*)d_in[9];
    const float* csp1  = (const float*)d_in[10];
    const float* csp2  = (const float*)d_in[11];
    const float* csp3  = (const float*)d_in[12];
    const float* clam  = (const float*)d_in[13];
    const float* cscal = (const float*)d_in[14];
    // n_out=2, n_in=6 fixed by setup_inputs (static loop counts for graph capture)

    float* x = (float*)d_out;

    float *t4,*t8,*msk2,*Bp,*pv,*pb1,*pb2;
    cudaGetSymbolAddress((void**)&t4,g_t4);
    cudaGetSymbolAddress((void**)&t8,g_t8);
    cudaGetSymbolAddress((void**)&msk2,g_mask2);
    cudaGetSymbolAddress((void**)&Bp,g_Bp);
    cudaGetSymbolAddress((void**)&pv,g_p);
    cudaGetSymbolAddress((void**)&pb1,g_partB1);
    cudaGetSymbolAddress((void**)&pb2,g_partB2);
    __nv_bfloat16 *t8h,*t8l,*ah,*al,*bh,*bl,*wbw,*wbm,*wb2,*wb3;
    cudaGetSymbolAddress((void**)&t8h,g_t8h);
    cudaGetSymbolAddress((void**)&t8l,g_t8l);
    cudaGetSymbolAddress((void**)&ah,g_ah);
    cudaGetSymbolAddress((void**)&al,g_al);
    cudaGetSymbolAddress((void**)&bh,g_bh);
    cudaGetSymbolAddress((void**)&bl,g_bl);
    cudaGetSymbolAddress((void**)&wbw,g_wb_w12);
    cudaGetSymbolAddress((void**)&wbm,g_wb_m12);
    cudaGetSymbolAddress((void**)&wb2,g_wb_m2);
    cudaGetSymbolAddress((void**)&wb3,g_wb_m3);

    const int EW_GRID = 512;

    wprep_k<<<58, 256>>>(w1_2, m1_2, m2w, m3w);
    wadjprep_k<<<162, 256>>>(w1_2);
    setup_k<<<1, 256>>>(sigma, clam, cscal);
    init_k<<<EW_GRID, 256>>>(x, y);

    auto tc9 = [&](int epi, const __nv_bfloat16* wbp, const float* spc, const float* mask){
        constexpr int smb = 16384 + 2*2*18432;   // 90112
        if (epi==1){
            cudaFuncSetAttribute(tconv9_k<1>, cudaFuncAttributeMaxDynamicSharedMemorySize, smb);
            tconv9_k<1><<<dim3(8,16,NB), 256, smb>>>(t8h, t8l, wbp, ah, al, spc, mask);
        } else {
            cudaFuncSetAttribute(tconv9_k<3>, cudaFuncAttributeMaxDynamicSharedMemorySize, smb);
            tconv9_k<3><<<dim3(8,16,NB), 256, smb>>>(t8h, t8l, wbp, ah, al, spc, mask);
        }
    };
    auto tc3 = [&](int epi, const __nv_bfloat16* ih, const __nv_bfloat16* il,
                   const __nv_bfloat16* wbp, float* of, __nv_bfloat16* oh, __nv_bfloat16* ol,
                   const float* spc){
        constexpr int smb = 1024 + 4*2*10240;    // 82944
        if (epi==1){
            cudaFuncSetAttribute(tconv3_k<1>, cudaFuncAttributeMaxDynamicSharedMemorySize, smb);
            tconv3_k<1><<<dim3(8,16,NB), 256, smb>>>(ih, il, wbp, of, oh, ol, spc);
        } else {
            cudaFuncSetAttribute(tconv3_k<2>, cudaFuncAttributeMaxDynamicSharedMemorySize, smb);
            tconv3_k<2><<<dim3(8,16,NB), 256, smb>>>(ih, il, wbp, of, oh, ol, spc);
        }
    };
    auto tadj = [&](){
        constexpr int smb = 384*272;             // 104448
        cudaFuncSetAttribute(tadj_k, cudaFuncAttributeMaxDynamicSharedMemorySize, smb);
        tadj_k<<<dim3(8,16,NB), 256, smb>>>(ah, al, t8);
    };

    // BtB(src)->dst
    auto btb = [&](const float* src, float* dst){
        CONV(9, 1, 4,   4, 1, 32, 1, false, false, 0, src, w1_0, t4, nullptr, nullptr, nullptr, nullptr);
        CONV(9, 4, 8,   8, 2, 16, 4, false, false, 4, t4,  w1_1, nullptr, nullptr, nullptr, t8h, t8l);
        tc9(3, wbw, nullptr, msk2);
        tadj();
        CONV(9, 8, 4,   4, 1, 16, 8, true, false, 0, t8,  w1_1, t4, nullptr, nullptr, nullptr, nullptr);
        CONV(9, 4, 1,   1, 1, 64, 4, true, false, 3, t4,  w1_0, dst, nullptr, src, nullptr, nullptr);
    };

    for (int outer=0; outer<N_OUT; ++outer){
        // cal_mask(x) -> g_mask2 (channel-last)
        CONV(9, 1, 4, 4, 1, 32, 1, false, false, 0, x,  m1_0, t4, nullptr, nullptr, nullptr, nullptr);
        CONV(9, 4, 8, 8, 2, 16, 4, false, false, 4, t4, m1_1, nullptr, nullptr, nullptr, t8h, t8l);
        tc9(1, wbm, csp1, nullptr);
        tc3(1, ah, al, wb2, nullptr, bh, bl, csp2);
        tc3(2, bh, bl, wb3, msk2, nullptr, nullptr, csp3);

        // CG init
        btb(x, Bp);
        resid_k<<<EW_GRID, 256>>>();

        for (int it=0; it<N_IN; ++it){
            float* oldp = (it&1) ? pb2 : pb1;
            float* newp = (it&1) ? pb1 : pb2;
            btb(pv, Bp);
            dotpb_k<<<NB*16, 256>>>();
            updxr_k<<<EW_GRID, 256>>>(x, oldp, newp);
            updp_k<<<EW_GRID, 256>>>(oldp, newp);
        }
    }
    (void)in_sizes; (void)n_in_args; (void)out_size;
}

// round 17
// speedup vs baseline: 1.4448x; 1.0352x over previous
#include <cuda_runtime.h>
#include <cuda_bf16.h>
#include <math.h>

#define NB 8
#define NPIX 16384
#define N_OUT 2
#define N_IN 6
typedef unsigned long long u64;
typedef unsigned int u32;
typedef unsigned short u16;

// ---------------- scratch (static device globals) ----------------
__device__ float g_t4[NB*4*NPIX];
__device__ float g_t8[NB*8*NPIX];
__device__ float g_mask2[NB*NPIX*128];          // channel-last [b][pix][128]
__device__ float g_b[NB*NPIX], g_r[NB*NPIX], g_p[NB*NPIX], g_Bp[NB*NPIX];
// channel-last bf16 hi/lo planes
__device__ __nv_bfloat16 g_t8h[NB*NPIX*8], g_t8l[NB*NPIX*8];
__device__ __nv_bfloat16 g_ah[NB*NPIX*128], g_al[NB*NPIX*128];
__device__ __nv_bfloat16 g_bh[NB*NPIX*128], g_bl[NB*NPIX*128];
// bf16 weight images for tconv: per chunk [hi 128x64][lo 128x64] row-major
__device__ __nv_bfloat16 g_wb_w12[11*2*8192], g_wb_m12[11*2*8192];
__device__ __nv_bfloat16 g_wb_m2 [18*2*8192], g_wb_m3 [18*2*8192];
// fragment-ordered adjoint weights: [81 tap][8 k16][32 lane][2 reg] u32
__device__ u32 g_wadj_h[41472], g_wadj_l[41472];
__device__ float g_lam[NB], g_inv1pl[NB], g_scaling[NB*128];
__device__ float g_partA[NB*16], g_partB1[NB*64], g_partB2[NB*64];

// ---------------- PTX helpers (baseline PTX only) ----------------
__device__ __forceinline__ u32 smem_u32(const void* p){
    u32 a; asm("{ .reg .u64 t; cvta.to.shared.u64 t, %1; cvt.u32.u64 %0, t; }":"=r"(a):"l"(p)); return a;
}
__device__ __forceinline__ void cp16(u32 dst, const void* src, bool pred){
    int sz = pred ? 16 : 0;
    asm volatile("cp.async.ca.shared.global [%0], [%1], 16, %2;"
                 :: "r"(dst), "l"(src), "r"(sz) : "memory");
}
__device__ __forceinline__ void cp_commit(){ asm volatile("cp.async.commit_group;":::"memory"); }
template<int N> __device__ __forceinline__ void cp_wait(){
    asm volatile("cp.async.wait_group %0;"::"n"(N):"memory");
}
__device__ __forceinline__ void ldsm4(u32* r, u32 addr){
    asm volatile("ldmatrix.sync.aligned.m8n8.x4.shared.b16 {%0,%1,%2,%3}, [%4];"
                 : "=r"(r[0]),"=r"(r[1]),"=r"(r[2]),"=r"(r[3]) : "r"(addr));
}
__device__ __forceinline__ void mma_bf16(float* c, const u32* a, const u32* b){
    asm volatile("mma.sync.aligned.m16n8k16.row.col.f32.bf16.bf16.f32 "
                 "{%0,%1,%2,%3}, {%4,%5,%6,%7}, {%8,%9}, {%0,%1,%2,%3};"
                 : "+f"(c[0]),"+f"(c[1]),"+f"(c[2]),"+f"(c[3])
                 : "r"(a[0]),"r"(a[1]),"r"(a[2]),"r"(a[3]), "r"(b[0]),"r"(b[1]));
}

// ---------------- splines / split ----------------
__device__ __forceinline__ float spline_gen(const float* __restrict__ c, int K,
                                            float xmin, float xmax, float x){
    float step=(xmax-xmin)/(float)(K-1);
    float t=(x-xmin)/step, f=floorf(t);
    f=fminf(fmaxf(f,0.0f),(float)(K-2));
    int i=(int)f; float fr=t-f;
    return fmaf(fr, c[i+1]-c[i], c[i]);
}
__device__ __forceinline__ float spline31(const float* __restrict__ c, float v){
    float t=v*10.0f, f=floorf(t);
    f=fminf(fmaxf(f,0.0f),29.0f);
    int i=(int)f; float fr=t-f;
    return fmaf(fr, c[i+1]-c[i], c[i]);
}
__device__ __forceinline__ void bfsplit(float v, u16& h, u16& l){
    __nv_bfloat16 hb=__float2bfloat16_rn(v);
    h=__bfloat16_as_ushort(hb);
    l=__bfloat16_as_ushort(__float2bfloat16_rn(v-__bfloat162float(hb)));
}

// ============ 9x9 CIN=8 fwd tconv: resident halo A, double-buffered B ============
// EPI: 1 = spline31(|v|) -> bf16 hi/lo channel-last,
//      3 = multiply by mask2 (channel-last fp32) -> bf16 hi/lo channel-last
template<int EPI>
__global__ void __launch_bounds__(256)
tconv9_k(const __nv_bfloat16* __restrict__ inh, const __nv_bfloat16* __restrict__ inl,
         const __nv_bfloat16* __restrict__ wb,
         __nv_bfloat16* __restrict__ outh, __nv_bfloat16* __restrict__ outl,
         const float* __restrict__ spc, const float* __restrict__ maskp)
{
    constexpr int HALO = 1024;
    constexpr int BB   = 16384;
    constexpr int BPL  = 18432;
    constexpr int BBUF = 2*BPL;

    extern __shared__ char s_raw[];
    const u32 sb = smem_u32(s_raw);
    float* hdr = (float*)s_raw;
    const int tid = threadIdx.x, wid = tid>>5, lid = tid&31;
    const int x0 = blockIdx.x*16, y0 = blockIdx.y*8, b = blockIdx.z;

    if (EPI==1 && tid<31) hdr[tid] = spc[tid];

    for (int i=tid; i<768; i+=256){
        int pl = (i>=384), px = i - pl*384;
        int iy = px/24, ix = px - iy*24;
        int gy = y0+iy-4, gx = x0+ix-4;
        bool ok = ((u32)gy<128u) && ((u32)gx<128u);
        const __nv_bfloat16* srcb = pl ? inl : inh;
        const void* src = ok ? (const void*)(srcb + ((b*128+gy)*128+gx)*8) : (const void*)srcb;
        cp16(sb + HALO + (u32)(pl*6400 + iy*400 + ix*16), src, ok);
    }
    auto stageB = [&](int c, int buf){
#pragma unroll
        for (int it=0; it<8; ++it){
            int idx = tid + it*256;
            int pl = idx>>10, r = idx&1023;
            int n = r>>3, s = r&7;
            const __nv_bfloat16* src = wb + c*16384 + pl*8192 + n*64 + s*8;
            cp16(sb + BB + (u32)(buf*BBUF + pl*BPL + n*144 + s*16), src, true);
        }
        cp_commit();
    };

    float acc[8][2][4];
#pragma unroll
    for (int i=0;i<8;++i)
#pragma unroll
        for (int j=0;j<2;++j)
#pragma unroll
            for (int k=0;k<4;++k) acc[i][j][k]=0.0f;

    const int rr = lid & 7, t = lid >> 3;
    const int mx = rr + (t&1)*8;
    const u32 bOff = (u32)((wid*16 + (t>>1)*8 + rr)*144 + (t&1)*16);

    stageB(0, 0);
#pragma unroll 1
    for (int c=0; c<11; ++c){
        const int buf = c&1;
        if (c+1 < 11){ stageB(c+1, buf^1); cp_wait<1>(); }
        else         { cp_wait<0>(); }
        __syncthreads();

        const u32 bH = sb + BB + buf*BBUF, bL = bH + BPL;
#pragma unroll
        for (int k16=0; k16<4; ++k16){
            u32 bh[4], bl[4];
            ldsm4(bh, bH + bOff + k16*32);
            ldsm4(bl, bL + bOff + k16*32);
            int ta = c*8 + k16*2, tb = ta + 1;
            if (ta>80) ta=80;
            if (tb>80) tb=80;
            int tap = (t>>1) ? tb : ta;
            int ky = tap/9, kx = tap - ky*9;
            const u32 aBase = sb + HALO + (u32)(ky*400 + (mx + kx)*16);
#pragma unroll
            for (int mt=0; mt<8; ++mt){
                u32 ah[4], al[4];
                ldsm4(ah, aBase + (u32)(mt*400));
                ldsm4(al, aBase + (u32)(mt*400) + 6400u);
                mma_bf16(acc[mt][0], ah, bh+0);
                mma_bf16(acc[mt][1], ah, bh+2);
                mma_bf16(acc[mt][0], al, bh+0);
                mma_bf16(acc[mt][1], al, bh+2);
                mma_bf16(acc[mt][0], ah, bl+0);
                mma_bf16(acc[mt][1], ah, bl+2);
            }
        }
        __syncthreads();
    }

    const int row = lid>>2, q = (lid&3)*2;
#pragma unroll
    for (int mt=0; mt<8; ++mt){
        const int gy = y0 + mt;
        const int gxa = x0 + row, gxb = gxa + 8;
#pragma unroll
        for (int nt=0; nt<2; ++nt){
            const int n = wid*16 + nt*8 + q;
            const int pa = (b*128+gy)*128+gxa, pb = (b*128+gy)*128+gxb;
            float v0 = acc[mt][nt][0], v1 = acc[mt][nt][1];
            float v2 = acc[mt][nt][2], v3 = acc[mt][nt][3];
            if (EPI==1){
                v0 = spline31(hdr, fabsf(v0)); v1 = spline31(hdr, fabsf(v1));
                v2 = spline31(hdr, fabsf(v2)); v3 = spline31(hdr, fabsf(v3));
            } else {
                float2 m0 = *(const float2*)(maskp + (long)pa*128 + n);
                float2 m1 = *(const float2*)(maskp + (long)pb*128 + n);
                v0 *= m0.x; v1 *= m0.y;
                v2 *= m1.x; v3 *= m1.y;
            }
            u16 h0,l0,h1,l1,h2,l2,h3,l3;
            bfsplit(v0,h0,l0); bfsplit(v1,h1,l1);
            bfsplit(v2,h2,l2); bfsplit(v3,h3,l3);
            *(u32*)(outh + (long)pa*128 + n) = (u32)h0 | ((u32)h1<<16);
            *(u32*)(outl + (long)pa*128 + n) = (u32)l0 | ((u32)l1<<16);
            *(u32*)(outh + (long)pb*128 + n) = (u32)h2 | ((u32)h3<<16);
            *(u32*)(outl + (long)pb*128 + n) = (u32)l2 | ((u32)l3<<16);
        }
    }
}

// ============ 3x3 CIN=128 tconv: 32-k chunks (pitch 80) ============
// EPI: 1 = spline31(|v|)->bf16 hi/lo channel-last, 2 = mask final -> fp32 channel-last
template<int EPI>
__global__ void __launch_bounds__(256)
tconv3_k(const __nv_bfloat16* __restrict__ inh, const __nv_bfloat16* __restrict__ inl,
         const __nv_bfloat16* __restrict__ wb, float* __restrict__ outf,
         __nv_bfloat16* __restrict__ outh, __nv_bfloat16* __restrict__ outl,
         const float* __restrict__ spc)
{
    constexpr int NKC   = 36;
    constexpr int HDR   = 1024;
    constexpr int PLANE = 128*80;
    constexpr int BUF   = 2*PLANE;
    constexpr int SM_A  = HDR;
    constexpr int SM_B  = HDR + 2*BUF;

    extern __shared__ char s_raw[];
    const u32 sb = smem_u32(s_raw);
    float* hdr = (float*)s_raw;
    const int tid = threadIdx.x, wid = tid>>5, lid = tid&31;
    const int x0 = blockIdx.x*16, y0 = blockIdx.y*8, b = blockIdx.z;

    if (tid<31) hdr[tid] = spc[tid];
    if (EPI==2 && tid>=64 && tid<192) hdr[32+tid-64] = g_scaling[b*128+tid-64];

    auto stage = [&](int c, int buf){
        const int tap = c>>2, q = c&3;
        const int ky = tap/3, kx = tap%3;
        const int c64 = c>>1, h = c&1;
#pragma unroll
        for (int it=0; it<4; ++it){
            int idx = tid + it*256;
            int pl = idx>>9, r = idx&511;
            int m = r>>2, s = r&3;
            int my = m>>4, mxx = m&15;
            const __nv_bfloat16* srcb = pl ? inl : inh;
            const void* src = srcb; bool ok = false;
            int gy = y0+my+ky-1, gx = x0+mxx+kx-1;
            if ((u32)gy<128u && (u32)gx<128u){
                ok = true; src = srcb + ((b*128+gy)*128+gx)*128 + q*32 + s*8;
            }
            cp16(sb + SM_A + buf*BUF + pl*PLANE + m*80 + s*16, src, ok);
        }
#pragma unroll
        for (int it=0; it<4; ++it){
            int idx = tid + it*256;
            int pl = idx>>9, r = idx&511;
            int n = r>>2, s = r&3;
            const __nv_bfloat16* src = wb + c64*16384 + pl*8192 + n*64 + h*32 + s*8;
            cp16(sb + SM_B + buf*BUF + pl*PLANE + n*80 + s*16, src, true);
        }
        cp_commit();
    };

    float acc[8][2][4];
#pragma unroll
    for (int i=0;i<8;++i)
#pragma unroll
        for (int j=0;j<2;++j)
#pragma unroll
            for (int k=0;k<4;++k) acc[i][j][k]=0.0f;

    const int rr = lid & 7, t = lid >> 3;
    const u32 aOff = (u32)((rr + (t&1)*8)*80 + (t>>1)*16);
    const u32 bOff = (u32)((wid*16 + (t>>1)*8 + rr)*80 + (t&1)*16);

    stage(0, 0);
#pragma unroll 1
    for (int c=0; c<NKC; ++c){
        const int buf = c&1;
        if (c+1 < NKC){ stage(c+1, buf^1); cp_wait<1>(); }
        else          { cp_wait<0>(); }
        __syncthreads();

        const u32 aH = sb + SM_A + buf*BUF, aL = aH + PLANE;
        const u32 bH = sb + SM_B + buf*BUF, bL = bH + PLANE;
#pragma unroll
        for (int k16=0; k16<2; ++k16){
            u32 bh[4], bl[4];
            ldsm4(bh, bH + bOff + k16*32);
            ldsm4(bl, bL + bOff + k16*32);
#pragma unroll
            for (int mt=0; mt<8; ++mt){
                u32 ah[4], al[4];
                ldsm4(ah, aH + aOff + mt*1280 + k16*32);
                ldsm4(al, aL + aOff + mt*1280 + k16*32);
                mma_bf16(acc[mt][0], ah, bh+0);
                mma_bf16(acc[mt][1], ah, bh+2);
                mma_bf16(acc[mt][0], al, bh+0);
                mma_bf16(acc[mt][1], al, bh+2);
                mma_bf16(acc[mt][0], ah, bl+0);
                mma_bf16(acc[mt][1], ah, bl+2);
            }
        }
        __syncthreads();
    }

    const int row = lid>>2, q = (lid&3)*2;
#pragma unroll
    for (int mt=0; mt<8; ++mt){
        const int gy = y0 + mt;
        const int gxa = x0 + row, gxb = gxa + 8;
#pragma unroll
        for (int nt=0; nt<2; ++nt){
            const int n = wid*16 + nt*8 + q;
            const int pa = (b*128+gy)*128+gxa, pb = (b*128+gy)*128+gxb;
            float v0 = acc[mt][nt][0], v1 = acc[mt][nt][1];
            float v2 = acc[mt][nt][2], v3 = acc[mt][nt][3];
            if (EPI==1){
                v0 = spline31(hdr, fabsf(v0)); v1 = spline31(hdr, fabsf(v1));
                v2 = spline31(hdr, fabsf(v2)); v3 = spline31(hdr, fabsf(v3));
                u16 h0,l0,h1,l1,h2,l2,h3,l3;
                bfsplit(v0,h0,l0); bfsplit(v1,h1,l1);
                bfsplit(v2,h2,l2); bfsplit(v3,h3,l3);
                *(u32*)(outh + (long)pa*128 + n) = (u32)h0 | ((u32)h1<<16);
                *(u32*)(outl + (long)pa*128 + n) = (u32)l0 | ((u32)l1<<16);
                *(u32*)(outh + (long)pb*128 + n) = (u32)h2 | ((u32)h3<<16);
                *(u32*)(outl + (long)pb*128 + n) = (u32)l2 | ((u32)l3<<16);
            } else {
                float s0 = hdr[32+n], s1 = hdr[32+n+1];
                v0 = spline31(hdr, s0*fabsf(v0)); v0 = fminf(fmaxf(v0,0.01f),1.0f); v0 *= v0;
                v1 = spline31(hdr, s1*fabsf(v1)); v1 = fminf(fmaxf(v1,0.01f),1.0f); v1 *= v1;
                v2 = spline31(hdr, s0*fabsf(v2)); v2 = fminf(fmaxf(v2,0.01f),1.0f); v2 *= v2;
                v3 = spline31(hdr, s1*fabsf(v3)); v3 = fminf(fmaxf(v3,0.01f),1.0f); v3 *= v3;
                float2 w0v; w0v.x=v0; w0v.y=v1;
                float2 w1v; w1v.x=v2; w1v.y=v3;
                *(float2*)(outf + (long)pa*128 + n) = w0v;
                *(float2*)(outf + (long)pb*128 + n) = w1v;
            }
        }
    }
}

// ============ adjoint conv 128->8 via mma.sync, ci split in 2 halves ============
// R17: 6 accumulators, two triples alternated by tap parity (double the acc
// re-use distance vs R16's 3-acc split), no weight prefetch (R15 spill lesson).
__global__ void __launch_bounds__(256)
tadj_k(const __nv_bfloat16* __restrict__ mh, const __nv_bfloat16* __restrict__ ml,
       float* __restrict__ out8)
{
    extern __shared__ char s_raw[];
    const u32 sb = smem_u32(s_raw);
    const int tid = threadIdx.x, wid = tid>>5, lid = tid&31;
    const int x0 = blockIdx.x*16, y0 = blockIdx.y*8, b = blockIdx.z;

    float a0[4]={0,0,0,0}, a1[4]={0,0,0,0}, a2[4]={0,0,0,0};
    float a3[4]={0,0,0,0}, a4[4]={0,0,0,0}, a5[4]={0,0,0,0};
    const int rr = lid&7, t = lid>>3;
    const int rowSel = rr + (t&1)*8;
    const u32 colSel = (u32)((t>>1)*16);

    const uint2* __restrict__ whv = (const uint2*)g_wadj_h;
    const uint2* __restrict__ wlv = (const uint2*)g_wadj_l;

#pragma unroll 1
    for (int h=0; h<2; ++h){
        for (int i=tid; i<6144; i+=256){
            int px = i>>4, r = i&15, pl = r>>3, seg = r&7;
            int iy = px/24, ix = px - iy*24;
            int gy = y0+iy-4, gx = x0+ix-4;
            bool ok = ((u32)gy<128u) && ((u32)gx<128u);
            const __nv_bfloat16* srcb = pl ? ml : mh;
            const void* src = ok ? (const void*)(srcb + (((long)(b*128+gy)*128+gx)*128 + h*64 + seg*8))
                                 : (const void*)srcb;
            cp16(sb + (u32)(px*272 + pl*128 + seg*16), src, ok);
        }
        cp_commit(); cp_wait<0>();
        __syncthreads();

#pragma unroll 1
        for (int tp=0; tp<40; ++tp){
            // even tap -> a0..a2
            {
                int tap = tp*2;
                int ky = tap/9, kx = tap - ky*9;
                const u32 base = sb + (u32)(((wid+ky)*24 + rowSel + kx)*272) + colSel;
                const uint2* bh = whv + tap*256 + h*128 + lid;
                const uint2* bl = wlv + tap*256 + h*128 + lid;
#pragma unroll
                for (int kk=0; kk<4; ++kk){
                    u32 ah[4], al[4];
                    ldsm4(ah, base + kk*32);
                    ldsm4(al, base + 128 + kk*32);
                    uint2 vh = __ldg(bh + kk*32);
                    uint2 vl = __ldg(bl + kk*32);
                    mma_bf16(a0, ah, (const u32*)&vh);
                    mma_bf16(a1, al, (const u32*)&vh);
                    mma_bf16(a2, ah, (const u32*)&vl);
                }
            }
            // odd tap -> a3..a5
            {
                int tap = tp*2 + 1;
                int ky = tap/9, kx = tap - ky*9;
                const u32 base = sb + (u32)(((wid+ky)*24 + rowSel + kx)*272) + colSel;
                const uint2* bh = whv + tap*256 + h*128 + lid;
                const uint2* bl = wlv + tap*256 + h*128 + lid;
#pragma unroll
                for (int kk=0; kk<4; ++kk){
                    u32 ah[4], al[4];
                    ldsm4(ah, base + kk*32);
                    ldsm4(al, base + 128 + kk*32);
                    uint2 vh = __ldg(bh + kk*32);
                    uint2 vl = __ldg(bl + kk*32);
                    mma_bf16(a3, ah, (const u32*)&vh);
                    mma_bf16(a4, al, (const u32*)&vh);
                    mma_bf16(a5, ah, (const u32*)&vl);
                }
            }
        }
        // last tap (80) -> a0..a2
        {
            int tap = 80;
            int ky = tap/9, kx = tap - ky*9;
            const u32 base = sb + (u32)(((wid+ky)*24 + rowSel + kx)*272) + colSel;
            const uint2* bh = whv + tap*256 + h*128 + lid;
            const uint2* bl = wlv + tap*256 + h*128 + lid;
#pragma unroll
            for (int kk=0; kk<4; ++kk){
                u32 ah[4], al[4];
                ldsm4(ah, base + kk*32);
                ldsm4(al, base + 128 + kk*32);
                uint2 vh = __ldg(bh + kk*32);
                uint2 vl = __ldg(bl + kk*32);
                mma_bf16(a0, ah, (const u32*)&vh);
                mma_bf16(a1, al, (const u32*)&vh);
                mma_bf16(a2, ah, (const u32*)&vl);
            }
        }
        __syncthreads();
    }

    const int xr = lid>>2, co = (lid&3)*2;
    const int gy = y0 + wid;
    float* o0 = out8 + ((b*8+co)*128 + gy)*128 + x0;
    float* o1 = o0 + NPIX;
    o0[xr]   = (((a0[0]+a1[0])+a2[0]) + ((a3[0]+a4[0])+a5[0]));
    o1[xr]   = (((a0[1]+a1[1])+a2[1]) + ((a3[1]+a4[1])+a5[1]));
    o0[xr+8] = (((a0[2]+a1[2])+a2[2]) + ((a3[2]+a4[2])+a5[2]));
    o1[xr+8] = (((a0[3]+a1[3])+a2[3]) + ((a3[3]+a4[3])+a5[3]));
}

// ============ weight prep: fwd chunk images ============
__global__ void wprep_k(const float* __restrict__ w12, const float* __restrict__ m12,
                        const float* __restrict__ m2,  const float* __restrict__ m3)
{
    int cb = blockIdx.x;
    const float* src; __nv_bfloat16* dst; int CIN, KK, c;
    if (cb<11){src=w12;dst=g_wb_w12;CIN=8;KK=81;c=cb;}
    else if (cb<22){src=m12;dst=g_wb_m12;CIN=8;KK=81;c=cb-11;}
    else if (cb<40){src=m2;dst=g_wb_m2;CIN=128;KK=9;c=cb-22;}
    else {src=m3;dst=g_wb_m3;CIN=128;KK=9;c=cb-40;}
    __nv_bfloat16* base = dst + c*16384;
    for (int e=threadIdx.x;e<8192;e+=256){
        int co=e>>6, kl=e&63, k=c*64+kl, tap=k/CIN, ci=k%CIN;
        float w = (tap<KK) ? src[(co*CIN+ci)*KK+tap] : 0.0f;
        u16 h,l; bfsplit(w,h,l);
        base[co*64+kl] = __ushort_as_bfloat16(h);
        base[8192 + co*64+kl] = __ushort_as_bfloat16(l);
    }
}

// ============ weight prep: adjoint fragment-ordered (flipped w1_2) ============
__global__ void wadjprep_k(const float* __restrict__ w12)
{
    int idx = blockIdx.x*256 + threadIdx.x;
    if (idx < 41472){
        int reg  = idx & 1;
        int lane = (idx>>1) & 31;
        int kk   = (idx>>6) & 7;
        int tap  = idx>>9;
        int n    = lane>>2;
        int k0   = (lane&3)*2 + reg*8;
        int c0   = kk*16 + k0, c1 = c0 + 1;
        float wa = w12[(c0*8 + n)*81 + (80 - tap)];
        float wb = w12[(c1*8 + n)*81 + (80 - tap)];
        u16 ha,la,hb,lb; bfsplit(wa,ha,la); bfsplit(wb,hb,lb);
        g_wadj_h[idx] = (u32)ha | ((u32)hb<<16);
        g_wadj_l[idx] = (u32)la | ((u32)lb<<16);
    }
}

// ---------------- scalar direct conv (small channel counts) ----------------
__device__ __forceinline__ u64 pack2(float a, float b){
    u64 r; asm("mov.b64 %0, {%1, %2};":"=l"(r):"f"(a),"f"(b)); return r;
}
__device__ __forceinline__ void unpack2(u64 v, float& a, float& b){
    asm("mov.b64 {%0, %1}, %2;":"=f"(a),"=f"(b):"l"(v));
}
__device__ __forceinline__ void fma2(u64& d, u64 a, u64 b){
    asm("fma.rn.f32x2 %0, %1, %2, %3;":"=l"(d):"l"(a),"l"(b),"l"(d));
}

// EPI: 0 = fp32 NCHW, 3 = BtB combine (COUT==1), 4 = bf16 hi/lo channel-last split
template<int KSZ, int CIN, int COUT, int CO_TILE, int OC, int TW, int CICH,
         bool TRANS, bool MUL, int EPI>
__global__ void __launch_bounds__(16*(TW/8)*(CO_TILE/OC))
conv_k(const float* __restrict__ in, const float* __restrict__ wgt,
       float* __restrict__ out, const float* __restrict__ mul,
       const float* __restrict__ xadd,
       __nv_bfloat16* __restrict__ bfh, __nv_bfloat16* __restrict__ bfl)
{
    constexpr int P=KSZ/2, KK=KSZ*KSZ, XG=TW/8, CG=CO_TILE/OC, NT=16*XG*CG;
    constexpr int R=16+KSZ-1, C=TW+KSZ-1, SC=C+1, NCH=CIN/CICH, WIN=8+KSZ-1;
    constexpr bool PACKED=((OC&1)==0);
    constexpr int O2=(OC+1)/2;

    extern __shared__ char s_raw[];
    float* smem = (float*)s_raw;
    float* s_in = smem;
    float* s_w  = s_in + CICH*R*SC;

    const int tid=threadIdx.x, cg=tid%CG, xg=(tid/CG)%XG, row=tid/(CG*XG);
    const int tx0=blockIdx.x*TW, ty0=blockIdx.y*16;
    const int b=blockIdx.z/(COUT/CO_TILE), coc=(blockIdx.z%(COUT/CO_TILE))*CO_TILE;

    float acc[8][OC]; u64 acc2[8][O2];
#pragma unroll
    for (int j=0;j<8;++j){
#pragma unroll
        for (int o=0;o<OC;++o) acc[j][o]=0.0f;
#pragma unroll
        for (int o=0;o<O2;++o) acc2[j][o]=0ull;
    }

#pragma unroll 1
    for (int ch=0; ch<NCH; ++ch){
        const int ci0 = ch*CICH;
        for (int i=tid;i<CICH*R*C;i+=NT){
            int ci=i/(R*C), rr=(i/C)%R, cc=i%C;
            int gy=ty0-P+rr, gx=tx0-P+cc;
            float v=0.0f;
            if (gy>=0&&gy<128&&gx>=0&&gx<128){
                int gi=((b*CIN+ci0+ci)*128+gy)*128+gx;
                v=in[gi]; if (MUL) v*=mul[gi];
            }
            s_in[(ci*R+rr)*SC+cc]=v;
        }
        for (int i=tid;i<CICH*KK*CO_TILE;i+=NT){
            int co=i%CO_TILE, tap=(i/CO_TILE)%KK, ci=i/(CO_TILE*KK);
            int gw = TRANS ? (((ci0+ci)*COUT+(coc+co))*KK+tap)
                           : (((coc+co)*CIN+(ci0+ci))*KK+tap);
            s_w[i]=wgt[gw];
        }
        __syncthreads();
#pragma unroll 1
        for (int ci=0;ci<CICH;++ci){
#pragma unroll 1
            for (int ky=0;ky<KSZ;++ky){
                const int rr = TRANS ? (row+(KSZ-1)-ky) : (row+ky);
                const float* rowp = &s_in[(ci*R+rr)*SC + xg*8];
                const float* wp = &s_w[(ci*KK+ky*KSZ)*CO_TILE + cg*OC];
                if (PACKED){
                    u64 win2[WIN];
#pragma unroll
                    for (int k=0;k<WIN;++k){ float v=rowp[k]; win2[k]=pack2(v,v); }
#pragma unroll
                    for (int kx=0;kx<KSZ;++kx){
                        u64 wv2[O2];
#pragma unroll
                        for (int o=0;o<O2;++o) wv2[o]=*(const u64*)(wp+kx*CO_TILE+2*o);
#pragma unroll
                        for (int j=0;j<8;++j){
                            const u64 iv2 = TRANS ? win2[j+(KSZ-1)-kx] : win2[j+kx];
#pragma unroll
                            for (int o=0;o<O2;++o) fma2(acc2[j][o], iv2, wv2[o]);
                        }
                    }
                } else {
                    float win[WIN];
#pragma unroll
                    for (int k=0;k<WIN;++k) win[k]=rowp[k];
#pragma unroll
                    for (int kx=0;kx<KSZ;++kx){
                        float wv[OC];
#pragma unroll
                        for (int o=0;o<OC;++o) wv[o]=wp[kx*CO_TILE+o];
#pragma unroll
                        for (int j=0;j<8;++j){
                            const float iv = TRANS ? win[j+(KSZ-1)-kx] : win[j+kx];
#pragma unroll
                            for (int o=0;o<OC;++o) acc[j][o]=fmaf(iv,wv[o],acc[j][o]);
                        }
                    }
                }
            }
        }
        __syncthreads();
    }
    if (PACKED){
#pragma unroll
        for (int j=0;j<8;++j)
#pragma unroll
            for (int o=0;o<O2;++o)
                unpack2(acc2[j][o], acc[j][2*o], acc[j][2*o+1<OC?2*o+1:0]);
    }
    const int y=ty0+row;
#pragma unroll
    for (int o=0;o<OC;++o){
        const int c=coc+cg*OC+o;
#pragma unroll
        for (int j=0;j<8;++j){
            const int xx=tx0+xg*8+j;
            float v=acc[j][o];
            if (EPI==4){
                u16 h,l; bfsplit(v,h,l);
                const int pix=(b*128+y)*128+xx;
                bfh[pix*COUT + c] = __ushort_as_bfloat16(h);
                bfl[pix*COUT + c] = __ushort_as_bfloat16(l);
            } else {
                if (EPI==3){
                    const int ii=(b*128+y)*128+xx;
                    v=(xadd[ii]+g_lam[b]*v)*g_inv1pl[b];
                }
                out[((b*COUT+c)*128+y)*128+xx]=v;
            }
        }
    }
}

// ---------------- small kernels ----------------
__global__ void setup_k(const float* __restrict__ sigma, const float* __restrict__ c_lam,
                        const float* __restrict__ c_scal)
{
    int t=threadIdx.x;
    if (t<NB){
        float l=spline_gen(c_lam,53,-1.0f,51.0f,sigma[t]);
        g_lam[t]=l; g_inv1pl[t]=1.0f/(1.0f+l);
    }
    for (int i=t;i<NB*128;i+=blockDim.x){
        int b=i>>7, c=i&127; float s=sigma[b];
        g_scaling[i]=expf(spline_gen(c_scal+c*14,14,-1.0f,51.0f,s))/(s+1e-5f);
    }
}
__global__ void init_k(float* __restrict__ x, const float* __restrict__ y){
    int i=blockIdx.x*blockDim.x+threadIdx.x;
    if (i<NB*NPIX){ x[i]=0.0f; g_b[i]=y[i]*g_inv1pl[i>>14]; }
}
// r = b - Bp; p = r; r^2 partials -> g_partB1
__global__ void resid_k(){
    __shared__ float red[256];
    int i=blockIdx.x*256+threadIdx.x;
    float r = g_b[i]-g_Bp[i];
    g_r[i]=r; g_p[i]=r;
    red[threadIdx.x]=r*r; __syncthreads();
    for (int st=128;st>0;st>>=1){ if (threadIdx.x<st) red[threadIdx.x]+=red[threadIdx.x+st]; __syncthreads(); }
    if (threadIdx.x==0) g_partB1[blockIdx.x]=red[0];
}
// 16-slice dot(p, Bp) -> g_partA
__global__ void dotpb_k(){
    __shared__ float red[256];
    int bslice=blockIdx.x;
    int base=(bslice>>4)*NPIX + (bslice&15)*1024;
    float s=0.0f;
#pragma unroll
    for (int j=0;j<4;++j){
        int idx=base+threadIdx.x+j*256;
        s=fmaf(g_p[idx],g_Bp[idx],s);
    }
    red[threadIdx.x]=s; __syncthreads();
    for (int st=128;st>0;st>>=1){ if (threadIdx.x<st) red[threadIdx.x]+=red[threadIdx.x+st]; __syncthreads(); }
    if (threadIdx.x==0) g_partA[bslice]=red[0];
}
// alpha inline; x += a p; r -= a Bp; new r^2 partials -> partNew
__global__ void updxr_k(float* __restrict__ x, const float* __restrict__ partOld,
                        float* __restrict__ partNew){
    __shared__ float red[256];
    int i=blockIdx.x*256+threadIdx.x;
    int b=i>>14;
    float rn=0.0f, den=0.0f;
#pragma unroll 1
    for (int j=0;j<64;++j) rn += partOld[b*64+j];
#pragma unroll 1
    for (int j=0;j<16;++j) den += g_partA[b*16+j];
    bool act = rn>1e-6f;
    float a = act ? rn/(act?den:1.0f) : 0.0f;
    x[i]=fmaf(a,g_p[i],x[i]);
    float r=fmaf(-a,g_Bp[i],g_r[i]);
    g_r[i]=r;
    red[threadIdx.x]=r*r; __syncthreads();
    for (int st=128;st>0;st>>=1){ if (threadIdx.x<st) red[threadIdx.x]+=red[threadIdx.x+st]; __syncthreads(); }
    if (threadIdx.x==0) partNew[blockIdx.x]=red[0];
}
// beta inline; p = r + beta p
__global__ void updp_k(const float* __restrict__ partOld, const float* __restrict__ partNew){
    int i=blockIdx.x*256+threadIdx.x;
    int b=i>>14;
    float rn=0.0f, rn2=0.0f;
#pragma unroll 1
    for (int j=0;j<64;++j){ rn += partOld[b*64+j]; rn2 += partNew[b*64+j]; }
    float beta=(rn>1e-6f)?rn2/rn:0.0f;
    g_p[i]=fmaf(beta,g_p[i],g_r[i]);
}

// ---------------- launch helpers ----------------
#define CONV(KSZ, CIN, COUT, COT, OC, TW, CICH, TR, MU, EPI, IN, W, OUT, MULP, XA, BH, BL) \
    do { \
        auto kfn = conv_k<KSZ, CIN, COUT, COT, OC, TW, CICH, TR, MU, EPI>; \
        constexpr int smb = ((CICH)*(16+(KSZ)-1)*((TW)+(KSZ)) + (CICH)*(KSZ)*(KSZ)*(COT) + 32)*4; \
        cudaFuncSetAttribute(kfn, cudaFuncAttributeMaxDynamicSharedMemorySize, smb); \
        dim3 gr(128/(TW), 8, NB*((COUT)/(COT))); \
        kfn<<<gr, 16*((TW)/8)*((COT)/(OC)), smb>>>(IN, W, OUT, MULP, XA, BH, BL); \
    } while (0)

extern "C" void kernel_launch(void* const* d_in, const int* in_sizes, int n_in_args,
                              void* d_out, int out_size)
{
    const float* y     = (const float*)d_in[0];
    const float* sigma = (const float*)d_in[1];
    const float* w1_0  = (const float*)d_in[2];
    const float* w1_1  = (const float*)d_in[3];
    const float* w1_2  = (const float*)d_in[4];
    const float* m1_0  = (const float*)d_in[5];
    const float* m1_1  = (const float*)d_in[6];
    const float* m1_2  = (const float*)d_in[7];
    const float* m2w   = (const float*)d_in[8];
    const float* m3w   = (const float*)d_in[9];
    const float* csp1  = (const float*)d_in[10];
    const float* csp2  = (const float*)d_in[11];
    const float* csp3  = (const float*)d_in[12];
    const float* clam  = (const float*)d_in[13];
    const float* cscal = (const float*)d_in[14];
    // n_out=2, n_in=6 fixed by setup_inputs (static loop counts for graph capture)

    float* x = (float*)d_out;

    float *t4,*t8,*msk2,*Bp,*pv,*pb1,*pb2;
    cudaGetSymbolAddress((void**)&t4,g_t4);
    cudaGetSymbolAddress((void**)&t8,g_t8);
    cudaGetSymbolAddress((void**)&msk2,g_mask2);
    cudaGetSymbolAddress((void**)&Bp,g_Bp);
    cudaGetSymbolAddress((void**)&pv,g_p);
    cudaGetSymbolAddress((void**)&pb1,g_partB1);
    cudaGetSymbolAddress((void**)&pb2,g_partB2);
    __nv_bfloat16 *t8h,*t8l,*ah,*al,*bh,*bl,*wbw,*wbm,*wb2,*wb3;
    cudaGetSymbolAddress((void**)&t8h,g_t8h);
    cudaGetSymbolAddress((void**)&t8l,g_t8l);
    cudaGetSymbolAddress((void**)&ah,g_ah);
    cudaGetSymbolAddress((void**)&al,g_al);
    cudaGetSymbolAddress((void**)&bh,g_bh);
    cudaGetSymbolAddress((void**)&bl,g_bl);
    cudaGetSymbolAddress((void**)&wbw,g_wb_w12);
    cudaGetSymbolAddress((void**)&wbm,g_wb_m12);
    cudaGetSymbolAddress((void**)&wb2,g_wb_m2);
    cudaGetSymbolAddress((void**)&wb3,g_wb_m3);

    const int EW_GRID = 512;

    wprep_k<<<58, 256>>>(w1_2, m1_2, m2w, m3w);
    wadjprep_k<<<162, 256>>>(w1_2);
    setup_k<<<1, 256>>>(sigma, clam, cscal);
    init_k<<<EW_GRID, 256>>>(x, y);

    auto tc9 = [&](int epi, const __nv_bfloat16* wbp, const float* spc, const float* mask){
        constexpr int smb = 16384 + 2*2*18432;   // 90112
        if (epi==1){
            cudaFuncSetAttribute(tconv9_k<1>, cudaFuncAttributeMaxDynamicSharedMemorySize, smb);
            tconv9_k<1><<<dim3(8,16,NB), 256, smb>>>(t8h, t8l, wbp, ah, al, spc, mask);
        } else {
            cudaFuncSetAttribute(tconv9_k<3>, cudaFuncAttributeMaxDynamicSharedMemorySize, smb);
            tconv9_k<3><<<dim3(8,16,NB), 256, smb>>>(t8h, t8l, wbp, ah, al, spc, mask);
        }
    };
    auto tc3 = [&](int epi, const __nv_bfloat16* ih, const __nv_bfloat16* il,
                   const __nv_bfloat16* wbp, float* of, __nv_bfloat16* oh, __nv_bfloat16* ol,
                   const float* spc){
        constexpr int smb = 1024 + 4*2*10240;    // 82944
        if (epi==1){
            cudaFuncSetAttribute(tconv3_k<1>, cudaFuncAttributeMaxDynamicSharedMemorySize, smb);
            tconv3_k<1><<<dim3(8,16,NB), 256, smb>>>(ih, il, wbp, of, oh, ol, spc);
        } else {
            cudaFuncSetAttribute(tconv3_k<2>, cudaFuncAttributeMaxDynamicSharedMemorySize, smb);
            tconv3_k<2><<<dim3(8,16,NB), 256, smb>>>(ih, il, wbp, of, oh, ol, spc);
        }
    };
    auto tadj = [&](){
        constexpr int smb = 384*272;             // 104448
        cudaFuncSetAttribute(tadj_k, cudaFuncAttributeMaxDynamicSharedMemorySize, smb);
        tadj_k<<<dim3(8,16,NB), 256, smb>>>(ah, al, t8);
    };

    // BtB(src)->dst
    auto btb = [&](const float* src, float* dst){
        CONV(9, 1, 4,   4, 1, 32, 1, false, false, 0, src, w1_0, t4, nullptr, nullptr, nullptr, nullptr);
        CONV(9, 4, 8,   8, 2, 16, 4, false, false, 4, t4,  w1_1, nullptr, nullptr, nullptr, t8h, t8l);
        tc9(3, wbw, nullptr, msk2);
        tadj();
        CONV(9, 8, 4,   4, 1, 16, 8, true, false, 0, t8,  w1_1, t4, nullptr, nullptr, nullptr, nullptr);
        CONV(9, 4, 1,   1, 1, 64, 4, true, false, 3, t4,  w1_0, dst, nullptr, src, nullptr, nullptr);
    };

    for (int outer=0; outer<N_OUT; ++outer){
        // cal_mask(x) -> g_mask2 (channel-last)
        CONV(9, 1, 4, 4, 1, 32, 1, false, false, 0, x,  m1_0, t4, nullptr, nullptr, nullptr, nullptr);
        CONV(9, 4, 8, 8, 2, 16, 4, false, false, 4, t4, m1_1, nullptr, nullptr, nullptr, t8h, t8l);
        tc9(1, wbm, csp1, nullptr);
        tc3(1, ah, al, wb2, nullptr, bh, bl, csp2);
        tc3(2, bh, bl, wb3, msk2, nullptr, nullptr, csp3);

        // CG init
        btb(x, Bp);
        resid_k<<<EW_GRID, 256>>>();

        for (int it=0; it<N_IN; ++it){
            float* oldp = (it&1) ? pb2 : pb1;
            float* newp = (it&1) ? pb1 : pb2;
            btb(pv, Bp);
            dotpb_k<<<NB*16, 256>>>();
            updxr_k<<<EW_GRID, 256>>>(x, oldp, newp);
            updp_k<<<EW_GRID, 256>>>(oldp, newp);
        }
    }
    (void)in_sizes; (void)n_in_args; (void)out_size;
}